// round 1
// baseline (speedup 1.0000x reference)
#include <cuda_runtime.h>

// Problem dims (fixed by the reference)
#define Bn 32
#define Sn 2048
#define En 1024
#define Hn 1024

// Scratch (allocation-free rule: __device__ globals)
__device__ float g_wq[Bn * Hn];      // W_q(dec_hidden)           [B,H]
__device__ float g_alpha[Bn * Sn];   // softmax(score)            [B,S]
__device__ float g_u[Bn * En];       // enc^T * alpha             [B,E]

// ---------------------------------------------------------------------------
// f32x2 packed-math helpers (FFMA2 — only reachable via PTX)
// ---------------------------------------------------------------------------
__device__ __forceinline__ unsigned long long pk2(float lo, float hi) {
    unsigned long long r;
    asm("mov.b64 %0, {%1, %2};" : "=l"(r) : "f"(lo), "f"(hi));
    return r;
}
__device__ __forceinline__ unsigned long long ffma2(unsigned long long a,
                                                    unsigned long long b,
                                                    unsigned long long c) {
    unsigned long long d;
    asm("fma.rn.f32x2 %0, %1, %2, %3;" : "=l"(d) : "l"(a), "l"(b), "l"(c));
    return d;
}
__device__ __forceinline__ float2 upk2(unsigned long long v) {
    float2 f;
    asm("mov.b64 {%0, %1}, %2;" : "=f"(f.x), "=f"(f.y) : "l"(v));
    return f;
}

// Accurate-enough fast tanh: 1 - 2/(exp(2x)+1). abs err ~2e-6, 2 MUFU.
__device__ __forceinline__ float tanh_fast(float x) {
    float e = __expf(2.0f * x);
    return 1.0f - __fdividef(2.0f, e + 1.0f);
}

// ---------------------------------------------------------------------------
// Kernel 1: wq[b,h] = dec[b,:] . W_q[h,:]   + zero the score output region
// grid (Hn/128, Bn), 128 threads
// ---------------------------------------------------------------------------
__global__ void k_wq(const float* __restrict__ dec,
                     const float* __restrict__ Wq,
                     float* __restrict__ score_out) {
    __shared__ float ds[En];
    const int b  = blockIdx.y;
    const int h0 = blockIdx.x * 128;
    const int tid = threadIdx.x;

    #pragma unroll
    for (int e = tid * 4; e < En; e += 512)
        *(float4*)&ds[e] = *(const float4*)&dec[b * En + e];

    // zero score[b, blockIdx.x*256 .. +255] (2 per thread): 8 blocks x 256 = Sn
    float2 z = make_float2(0.f, 0.f);
    *(float2*)&score_out[b * Sn + blockIdx.x * 256 + tid * 2] = z;

    __syncthreads();

    const int h = h0 + tid;
    const float* w = Wq + (size_t)h * En;
    float acc = 0.f;
    #pragma unroll 4
    for (int e = 0; e < En; e += 4) {
        float4 w4 = *(const float4*)&w[e];
        acc += w4.x * ds[e] + w4.y * ds[e + 1] + w4.z * ds[e + 2] + w4.w * ds[e + 3];
    }
    g_wq[b * Hn + h] = acc;
}

// ---------------------------------------------------------------------------
// Kernel 2: fused GEMM + tanh + V-reduction (ctx never hits memory)
//   ctx_tile[s,h] = enc[b,s,:] . W_k[h,:]
//   score[b,s]   += sum_h V[h] * tanh(ctx + wq[b,h])
// Tile: BM=64 (s) x BN=128 (h) x BK=16, 256 threads, thread tile 4x8 (f32x2).
// grid (Sn/64, Hn/128, Bn)
// ---------------------------------------------------------------------------
#define BM 64
#define BN 128
#define BK 16

__global__ __launch_bounds__(256, 2)
void k_ctx_score(const float* __restrict__ enc,
                 const float* __restrict__ Wk,
                 const float* __restrict__ Vv,
                 float* __restrict__ score) {
    __shared__ float As[BK][BM];
    __shared__ float Bs[BK][BN];
    __shared__ float red[BM][17];

    const int b  = blockIdx.z;
    const int s0 = blockIdx.x * BM;
    const int h0 = blockIdx.y * BN;
    const int tid = threadIdx.x;
    const int tx = tid & 15;   // h-dir: 8 outputs
    const int ty = tid >> 4;   // s-dir: 4 outputs

    const float* Ag = enc + ((size_t)b * Sn + s0) * En;
    const float* Bg = Wk + (size_t)h0 * En;

    const int lr = tid >> 2;          // 0..63
    const int lc = (tid & 3) << 2;    // 0,4,8,12

    unsigned long long acc[4][4];     // [i=s][jp=h-pair]
    #pragma unroll
    for (int i = 0; i < 4; i++)
        #pragma unroll
        for (int j = 0; j < 4; j++) acc[i][j] = 0ULL;

    for (int k0 = 0; k0 < En; k0 += BK) {
        float4 a  = *(const float4*)(Ag + (size_t)lr * En + k0 + lc);
        float4 w0 = *(const float4*)(Bg + (size_t)lr * En + k0 + lc);
        float4 w1 = *(const float4*)(Bg + (size_t)(lr + 64) * En + k0 + lc);
        As[lc + 0][lr] = a.x;  As[lc + 1][lr] = a.y;
        As[lc + 2][lr] = a.z;  As[lc + 3][lr] = a.w;
        Bs[lc + 0][lr] = w0.x; Bs[lc + 1][lr] = w0.y;
        Bs[lc + 2][lr] = w0.z; Bs[lc + 3][lr] = w0.w;
        Bs[lc + 0][lr + 64] = w1.x; Bs[lc + 1][lr + 64] = w1.y;
        Bs[lc + 2][lr + 64] = w1.z; Bs[lc + 3][lr + 64] = w1.w;
        __syncthreads();

        #pragma unroll
        for (int k = 0; k < BK; k++) {
            float4 av = *(const float4*)&As[k][ty * 4];
            double2 bd0 = *(const double2*)&Bs[k][tx * 8];
            double2 bd1 = *(const double2*)&Bs[k][tx * 8 + 4];
            unsigned long long b01 = __double_as_longlong(bd0.x);
            unsigned long long b23 = __double_as_longlong(bd0.y);
            unsigned long long b45 = __double_as_longlong(bd1.x);
            unsigned long long b67 = __double_as_longlong(bd1.y);
            #pragma unroll
            for (int i = 0; i < 4; i++) {
                float ai = (&av.x)[i];
                unsigned long long ad = pk2(ai, ai);
                acc[i][0] = ffma2(ad, b01, acc[i][0]);
                acc[i][1] = ffma2(ad, b23, acc[i][1]);
                acc[i][2] = ffma2(ad, b45, acc[i][2]);
                acc[i][3] = ffma2(ad, b67, acc[i][3]);
            }
        }
        __syncthreads();
    }

    // Epilogue: p[i] = sum over this thread's 8 h of V[h]*tanh(ctx + wq[b,h])
    const float* wqb = g_wq + b * Hn + h0 + tx * 8;
    const float* vb  = Vv + h0 + tx * 8;
    float p[4] = {0.f, 0.f, 0.f, 0.f};
    #pragma unroll
    for (int jp = 0; jp < 4; jp++) {
        float wq0 = wqb[jp * 2 + 0], wq1 = wqb[jp * 2 + 1];
        float v0  = vb[jp * 2 + 0],  v1  = vb[jp * 2 + 1];
        #pragma unroll
        for (int i = 0; i < 4; i++) {
            float2 c = upk2(acc[i][jp]);
            p[i] += v0 * tanh_fast(c.x + wq0) + v1 * tanh_fast(c.y + wq1);
        }
    }
    #pragma unroll
    for (int i = 0; i < 4; i++) red[ty * 4 + i][tx] = p[i];
    __syncthreads();
    if (tid < BM) {
        float sum = 0.f;
        #pragma unroll
        for (int t = 0; t < 16; t++) sum += red[tid][t];
        atomicAdd(&score[b * Sn + s0 + tid], sum);
    }
}

// ---------------------------------------------------------------------------
// Kernel 3: per-batch softmax over S -> g_alpha; also zero g_u for pass 4.
// grid (Bn), 256 threads
// ---------------------------------------------------------------------------
__global__ void k_softmax(const float* __restrict__ score) {
    __shared__ float sh[256];
    const int b = blockIdx.x;
    const int tid = threadIdx.x;

    float vals[8];
    float lmax = -3.4e38f;
    #pragma unroll
    for (int i = 0; i < 8; i++) {
        vals[i] = score[b * Sn + tid + i * 256];
        lmax = fmaxf(lmax, vals[i]);
    }
    sh[tid] = lmax;
    __syncthreads();
    for (int off = 128; off > 0; off >>= 1) {
        if (tid < off) sh[tid] = fmaxf(sh[tid], sh[tid + off]);
        __syncthreads();
    }
    const float m = sh[0];
    __syncthreads();

    float lsum = 0.f;
    #pragma unroll
    for (int i = 0; i < 8; i++) {
        vals[i] = __expf(vals[i] - m);
        lsum += vals[i];
    }
    sh[tid] = lsum;
    __syncthreads();
    for (int off = 128; off > 0; off >>= 1) {
        if (tid < off) sh[tid] += sh[tid + off];
        __syncthreads();
    }
    const float inv = 1.0f / sh[0];
    #pragma unroll
    for (int i = 0; i < 8; i++)
        g_alpha[b * Sn + tid + i * 256] = vals[i] * inv;

    for (int e = tid; e < En; e += 256) g_u[b * En + e] = 0.f;
}

// ---------------------------------------------------------------------------
// Kernel 4: u[b,e] = sum_s alpha[b,s] * enc[b,s,e]   (268 MB streaming read)
// grid (En/512, Sn/128, Bn), 128 threads, float4 per thread
// ---------------------------------------------------------------------------
__global__ void k_wenc(const float* __restrict__ enc) {
    const int b  = blockIdx.z;
    const int sc = blockIdx.y * 128;
    const int e0 = blockIdx.x * 512 + threadIdx.x * 4;

    const float* ep = enc + ((size_t)b * Sn + sc) * En + e0;
    const float* ap = g_alpha + b * Sn + sc;

    float4 acc = make_float4(0.f, 0.f, 0.f, 0.f);
    #pragma unroll 4
    for (int s = 0; s < 128; s++) {
        float a = ap[s];
        float4 v = *(const float4*)(ep + (size_t)s * En);
        acc.x += a * v.x; acc.y += a * v.y;
        acc.z += a * v.z; acc.w += a * v.w;
    }
    atomicAdd(&g_u[b * En + e0 + 0], acc.x);
    atomicAdd(&g_u[b * En + e0 + 1], acc.y);
    atomicAdd(&g_u[b * En + e0 + 2], acc.z);
    atomicAdd(&g_u[b * En + e0 + 3], acc.w);
}

// ---------------------------------------------------------------------------
// Kernel 5: hidden[b,h] = W_k[h,:] . u[b,:]
// grid (Hn/128, Bn), 128 threads
// ---------------------------------------------------------------------------
__global__ void k_hidden(const float* __restrict__ Wk, float* __restrict__ hid) {
    __shared__ float us[En];
    const int b = blockIdx.y;
    const int h = blockIdx.x * 128 + threadIdx.x;

    #pragma unroll
    for (int e = threadIdx.x * 4; e < En; e += 512)
        *(float4*)&us[e] = *(const float4*)&g_u[b * En + e];
    __syncthreads();

    const float* w = Wk + (size_t)h * En;
    float acc = 0.f;
    #pragma unroll 4
    for (int e = 0; e < En; e += 4) {
        float4 w4 = *(const float4*)&w[e];
        acc += w4.x * us[e] + w4.y * us[e + 1] + w4.z * us[e + 2] + w4.w * us[e + 3];
    }
    hid[b * Hn + h] = acc;
}

// ---------------------------------------------------------------------------
// Launch: 5 ordered kernels on the default stream (graph-capturable,
// allocation-free; scratch lives in __device__ globals).
// Output layout: [ hidden_state (B*H) | score (B*S) ]
// ---------------------------------------------------------------------------
extern "C" void kernel_launch(void* const* d_in, const int* in_sizes, int n_in,
                              void* d_out, int out_size) {
    const float* enc = (const float*)d_in[0];   // [B,S,E]
    const float* dec = (const float*)d_in[1];   // [B,E]
    const float* Wk  = (const float*)d_in[2];   // [H,E]
    const float* Wq  = (const float*)d_in[3];   // [H,E]
    const float* V   = (const float*)d_in[4];   // [H]

    float* out   = (float*)d_out;
    float* hid   = out;              // B*H
    float* score = out + Bn * Hn;    // B*S

    k_wq<<<dim3(Hn / 128, Bn), 128>>>(dec, Wq, score);
    k_ctx_score<<<dim3(Sn / BM, Hn / BN, Bn), 256>>>(enc, Wk, V, score);
    k_softmax<<<Bn, 256>>>(score);
    k_wenc<<<dim3(En / 512, Sn / 128, Bn), 128>>>(enc);
    k_hidden<<<dim3(Hn / 128, Bn), 128>>>(Wk, hid);
}

// round 3
// speedup vs baseline: 2.0341x; 2.0341x over previous
#include <cuda_runtime.h>
#include <cstdint>

// Problem dims (fixed by the reference)
#define Bn 32
#define Sn 2048
#define En 1024
#define Hn 1024

// ---------------------------------------------------------------------------
// Scratch (allocation-free rule: __device__ globals)
// ---------------------------------------------------------------------------
__device__ float g_wq[Bn * Hn];      // W_q(dec_hidden)  [B,H]
__device__ float g_alpha[Bn * Sn];   // softmax(score)   [B,S]
__device__ float g_u[Bn * En];       // enc^T * alpha    [B,E]

// ---------------------------------------------------------------------------
// Helpers
// ---------------------------------------------------------------------------
__device__ __forceinline__ float tf32_rna(float x) {
    uint32_t u;
    asm("cvt.rna.tf32.f32 %0, %1;" : "=r"(u) : "f"(x));
    return __uint_as_float(u);
}
__device__ __forceinline__ void tf32_split(float x, float& h, float& l) {
    h = tf32_rna(x);
    l = tf32_rna(x - h);
}

// m16n8k8 tf32 mma, D += A*B (row.col), fp32 accumulate. sm_80 baseline PTX.
__device__ __forceinline__ void mma_tf32(float* d, const float* a, const float* b) {
    asm volatile(
        "mma.sync.aligned.m16n8k8.row.col.f32.tf32.tf32.f32 "
        "{%0,%1,%2,%3}, {%4,%5,%6,%7}, {%8,%9}, {%0,%1,%2,%3};"
        : "+f"(d[0]), "+f"(d[1]), "+f"(d[2]), "+f"(d[3])
        : "r"(__float_as_uint(a[0])), "r"(__float_as_uint(a[1])),
          "r"(__float_as_uint(a[2])), "r"(__float_as_uint(a[3])),
          "r"(__float_as_uint(b[0])), "r"(__float_as_uint(b[1])));
}

// Accurate fast tanh: 1 - 2/(exp(2x)+1). abs err ~2e-6, 2 MUFU.
__device__ __forceinline__ float tanh_fast(float x) {
    float e = __expf(2.0f * x);
    return 1.0f - __fdividef(2.0f, e + 1.0f);
}

// ---------------------------------------------------------------------------
// Kernel 1: wq[b,h] = dec[b,:] . W_q[h,:]   + zero the score output region
// grid (Hn/128, Bn), 128 threads
// ---------------------------------------------------------------------------
__global__ void k_wq(const float* __restrict__ dec,
                     const float* __restrict__ Wq,
                     float* __restrict__ score_out) {
    __shared__ float ds[En];
    const int b  = blockIdx.y;
    const int h0 = blockIdx.x * 128;
    const int tid = threadIdx.x;

    #pragma unroll
    for (int e = tid * 4; e < En; e += 512)
        *(float4*)&ds[e] = *(const float4*)&dec[b * En + e];

    float2 z = make_float2(0.f, 0.f);
    *(float2*)&score_out[b * Sn + blockIdx.x * 256 + tid * 2] = z;

    __syncthreads();

    const int h = h0 + tid;
    const float* w = Wq + (size_t)h * En;
    float acc = 0.f;
    #pragma unroll 4
    for (int e = 0; e < En; e += 4) {
        float4 w4 = *(const float4*)&w[e];
        acc += w4.x * ds[e] + w4.y * ds[e + 1] + w4.z * ds[e + 2] + w4.w * ds[e + 3];
    }
    g_wq[b * Hn + h] = acc;
}

// ---------------------------------------------------------------------------
// Kernel 2: tf32x3 GEMM (mma.sync) + fused tanh/V epilogue.
//   ctx[s,h] = enc[b,s,:] . Wk[h,:]   (hi/lo split in-kernel, 3 mma passes)
//   score[b,s] += sum_h V[h] * tanh(ctx + wq[b,h])
// Tile 128(s) x 128(h) x 32(k). 256 threads = 8 warps (4m x 2n),
// warp tile 32x64 via m16n8k8. smem rows padded to 36 floats
// (conflict-free fragment lds; 2-way on STS only).
// grid (Sn/128=16, Hn/128=8, Bn=32)
// ---------------------------------------------------------------------------
#define TM 128
#define TN 128
#define TK 32
#define PAD 36          // floats per smem row (32 data + 4 pad)

__global__ void __launch_bounds__(256, 1)
k_gemm(const float* __restrict__ enc,
       const float* __restrict__ Wk,
       const float* __restrict__ Vv,
       float* __restrict__ score) {
    extern __shared__ float sm[];
    float* Ah = sm;                    // [128][PAD]
    float* Al = Ah + TM * PAD;
    float* Bh = Al + TM * PAD;
    float* Bl = Bh + TN * PAD;
    float* sV = Bl + TN * PAD;         // [128]
    float* sW = sV + TN;               // [128]
    float* sred = sW + TN;             // [128][2]

    const int tid = threadIdx.x;
    const int wid = tid >> 5;
    const int lane = tid & 31;
    const int g   = lane >> 2;         // 0..7
    const int tig = lane & 3;          // 0..3
    const int wm  = wid >> 1;          // 0..3  (m: 32 rows each)
    const int wn  = wid & 1;           // 0..1  (n: 64 cols each)

    const int s0 = blockIdx.x * TM;
    const int h0 = blockIdx.y * TN;
    const int b  = blockIdx.z;

    // Stage V and wq tiles
    if (tid < TN) {
        sV[tid] = Vv[h0 + tid];
        sW[tid] = g_wq[b * Hn + h0 + tid];
    }

    // Global load mapping: row = tid/2 (0..127), colbase = (tid&1)*16
    const int row = tid >> 1;
    const int cb  = (tid & 1) * 16;
    const float* aPtr = enc + ((size_t)(b * Sn + s0 + row)) * En + cb;
    const float* bPtr = Wk  + ((size_t)(h0 + row)) * En + cb;

    float acc[2][8][4];
    #pragma unroll
    for (int mt = 0; mt < 2; mt++)
        #pragma unroll
        for (int nt = 0; nt < 8; nt++)
            #pragma unroll
            for (int r = 0; r < 4; r++) acc[mt][nt][r] = 0.f;

    // Prologue LDG of chunk 0
    float4 ar[4], br[4];
    #pragma unroll
    for (int i = 0; i < 4; i++) {
        ar[i] = *(const float4*)(aPtr + i * 4);
        br[i] = *(const float4*)(bPtr + i * 4);
    }

    const int NCHUNK = En / TK;   // 32
    for (int c = 0; c < NCHUNK; c++) {
        // Convert + STS current chunk
        #pragma unroll
        for (int i = 0; i < 4; i++) {
            float4 h4, l4;
            tf32_split(ar[i].x, h4.x, l4.x);
            tf32_split(ar[i].y, h4.y, l4.y);
            tf32_split(ar[i].z, h4.z, l4.z);
            tf32_split(ar[i].w, h4.w, l4.w);
            *(float4*)&Ah[row * PAD + cb + i * 4] = h4;
            *(float4*)&Al[row * PAD + cb + i * 4] = l4;
            tf32_split(br[i].x, h4.x, l4.x);
            tf32_split(br[i].y, h4.y, l4.y);
            tf32_split(br[i].z, h4.z, l4.z);
            tf32_split(br[i].w, h4.w, l4.w);
            *(float4*)&Bh[row * PAD + cb + i * 4] = h4;
            *(float4*)&Bl[row * PAD + cb + i * 4] = l4;
        }
        __syncthreads();

        // Prefetch next chunk (overlaps with mma below)
        if (c + 1 < NCHUNK) {
            const int k0 = (c + 1) * TK;
            #pragma unroll
            for (int i = 0; i < 4; i++) {
                ar[i] = *(const float4*)(aPtr + k0 + i * 4);
                br[i] = *(const float4*)(bPtr + k0 + i * 4);
            }
        }

        // Compute: 4 k-steps of 8
        #pragma unroll
        for (int ks = 0; ks < 4; ks++) {
            const int ko = ks * 8;
            float aH[2][4], aL[2][4];
            #pragma unroll
            for (int mt = 0; mt < 2; mt++) {
                const int mr = wm * 32 + mt * 16;
                aH[mt][0] = Ah[(mr + g)     * PAD + ko + tig];
                aH[mt][1] = Ah[(mr + g + 8) * PAD + ko + tig];
                aH[mt][2] = Ah[(mr + g)     * PAD + ko + tig + 4];
                aH[mt][3] = Ah[(mr + g + 8) * PAD + ko + tig + 4];
                aL[mt][0] = Al[(mr + g)     * PAD + ko + tig];
                aL[mt][1] = Al[(mr + g + 8) * PAD + ko + tig];
                aL[mt][2] = Al[(mr + g)     * PAD + ko + tig + 4];
                aL[mt][3] = Al[(mr + g + 8) * PAD + ko + tig + 4];
            }
            float bH[8][2], bL[8][2];
            #pragma unroll
            for (int nt = 0; nt < 8; nt++) {
                const int nr = wn * 64 + nt * 8;
                bH[nt][0] = Bh[(nr + g) * PAD + ko + tig];
                bH[nt][1] = Bh[(nr + g) * PAD + ko + tig + 4];
                bL[nt][0] = Bl[(nr + g) * PAD + ko + tig];
                bL[nt][1] = Bl[(nr + g) * PAD + ko + tig + 4];
            }
            #pragma unroll
            for (int mt = 0; mt < 2; mt++)
                #pragma unroll
                for (int nt = 0; nt < 8; nt++) {
                    mma_tf32(acc[mt][nt], aH[mt], bH[nt]);  // hi*hi
                    mma_tf32(acc[mt][nt], aH[mt], bL[nt]);  // hi*lo
                    mma_tf32(acc[mt][nt], aL[mt], bH[nt]);  // lo*hi
                }
        }
        __syncthreads();
    }

    // ---- Epilogue: score[b, s] += sum_h V[h]*tanh(ctx + wq[h]) ----
    // Thread holds rows: wm*32 + mt*16 + {0,8} + g; cols: wn*64 + nt*8 + 2*tig + {0,1}
    float p[4] = {0.f, 0.f, 0.f, 0.f};
    #pragma unroll
    for (int mt = 0; mt < 2; mt++)
        #pragma unroll
        for (int nt = 0; nt < 8; nt++) {
            const int hl = wn * 64 + nt * 8 + 2 * tig;
            const float v0 = sV[hl], v1 = sV[hl + 1];
            const float w0 = sW[hl], w1 = sW[hl + 1];
            p[mt * 2 + 0] += v0 * tanh_fast(acc[mt][nt][0] + w0)
                           + v1 * tanh_fast(acc[mt][nt][1] + w1);
            p[mt * 2 + 1] += v0 * tanh_fast(acc[mt][nt][2] + w0)
                           + v1 * tanh_fast(acc[mt][nt][3] + w1);
        }
    // quad reduce (lanes with same g are consecutive: lane = g*4+tig)
    #pragma unroll
    for (int o = 1; o < 4; o <<= 1) {
        #pragma unroll
        for (int i = 0; i < 4; i++)
            p[i] += __shfl_xor_sync(0xFFFFFFFFu, p[i], o);
    }
    if (tig == 0) {
        #pragma unroll
        for (int mt = 0; mt < 2; mt++)
            #pragma unroll
            for (int hf = 0; hf < 2; hf++) {
                const int r = wm * 32 + mt * 16 + hf * 8 + g;
                sred[r * 2 + wn] = p[mt * 2 + hf];
            }
    }
    __syncthreads();
    if (tid < TM)
        atomicAdd(&score[b * Sn + s0 + tid], sred[tid * 2] + sred[tid * 2 + 1]);
}

#define GEMM_SMEM ((4 * TM * PAD + 2 * TN + 2 * TM) * 4)

// ---------------------------------------------------------------------------
// Kernel 3: per-batch softmax over S -> g_alpha; also zero g_u.
// ---------------------------------------------------------------------------
__global__ void k_softmax(const float* __restrict__ score) {
    __shared__ float sh[256];
    const int b = blockIdx.x;
    const int tid = threadIdx.x;

    float vals[8];
    float lmax = -3.4e38f;
    #pragma unroll
    for (int i = 0; i < 8; i++) {
        vals[i] = score[b * Sn + tid + i * 256];
        lmax = fmaxf(lmax, vals[i]);
    }
    sh[tid] = lmax;
    __syncthreads();
    for (int off = 128; off > 0; off >>= 1) {
        if (tid < off) sh[tid] = fmaxf(sh[tid], sh[tid + off]);
        __syncthreads();
    }
    const float m = sh[0];
    __syncthreads();

    float lsum = 0.f;
    #pragma unroll
    for (int i = 0; i < 8; i++) {
        vals[i] = __expf(vals[i] - m);
        lsum += vals[i];
    }
    sh[tid] = lsum;
    __syncthreads();
    for (int off = 128; off > 0; off >>= 1) {
        if (tid < off) sh[tid] += sh[tid + off];
        __syncthreads();
    }
    const float inv = 1.0f / sh[0];
    #pragma unroll
    for (int i = 0; i < 8; i++)
        g_alpha[b * Sn + tid + i * 256] = vals[i] * inv;

    for (int e = tid; e < En; e += 256) g_u[b * En + e] = 0.f;
}

// ---------------------------------------------------------------------------
// Kernel 4: u[b,e] = sum_s alpha[b,s] * enc[b,s,e]
// ---------------------------------------------------------------------------
__global__ void k_wenc(const float* __restrict__ enc) {
    const int b  = blockIdx.z;
    const int sc = blockIdx.y * 128;
    const int e0 = blockIdx.x * 512 + threadIdx.x * 4;

    const float* ep = enc + ((size_t)b * Sn + sc) * En + e0;
    const float* ap = g_alpha + b * Sn + sc;

    float4 acc = make_float4(0.f, 0.f, 0.f, 0.f);
    #pragma unroll 4
    for (int s = 0; s < 128; s++) {
        float a = ap[s];
        float4 v = *(const float4*)(ep + (size_t)s * En);
        acc.x += a * v.x; acc.y += a * v.y;
        acc.z += a * v.z; acc.w += a * v.w;
    }
    atomicAdd(&g_u[b * En + e0 + 0], acc.x);
    atomicAdd(&g_u[b * En + e0 + 1], acc.y);
    atomicAdd(&g_u[b * En + e0 + 2], acc.z);
    atomicAdd(&g_u[b * En + e0 + 3], acc.w);
}

// ---------------------------------------------------------------------------
// Kernel 5: hidden[b,h] = W_k[h,:] . u[b,:]
// ---------------------------------------------------------------------------
__global__ void k_hidden(const float* __restrict__ Wk, float* __restrict__ hid) {
    __shared__ float us[En];
    const int b = blockIdx.y;
    const int h = blockIdx.x * 128 + threadIdx.x;

    #pragma unroll
    for (int e = threadIdx.x * 4; e < En; e += 512)
        *(float4*)&us[e] = *(const float4*)&g_u[b * En + e];
    __syncthreads();

    const float* w = Wk + (size_t)h * En;
    float acc = 0.f;
    #pragma unroll 4
    for (int e = 0; e < En; e += 4) {
        float4 w4 = *(const float4*)&w[e];
        acc += w4.x * us[e] + w4.y * us[e + 1] + w4.z * us[e + 2] + w4.w * us[e + 3];
    }
    hid[b * Hn + h] = acc;
}

// ---------------------------------------------------------------------------
// Launch: 5 ordered kernels, default stream. Graph-capturable, allocation-free.
// Output layout: [ hidden_state (B*H) | score (B*S) ]
// ---------------------------------------------------------------------------
extern "C" void kernel_launch(void* const* d_in, const int* in_sizes, int n_in,
                              void* d_out, int out_size) {
    const float* enc = (const float*)d_in[0];   // [B,S,E]
    const float* dec = (const float*)d_in[1];   // [B,E]
    const float* Wk  = (const float*)d_in[2];   // [H,E]
    const float* Wq  = (const float*)d_in[3];   // [H,E]
    const float* V   = (const float*)d_in[4];   // [H]

    float* out   = (float*)d_out;
    float* hid   = out;              // B*H
    float* score = out + Bn * Hn;    // B*S

    static bool attr_set = false;
    if (!attr_set) {
        cudaFuncSetAttribute(k_gemm, cudaFuncAttributeMaxDynamicSharedMemorySize,
                             GEMM_SMEM);
        attr_set = true;
    }

    k_wq<<<dim3(Hn / 128, Bn), 128>>>(dec, Wq, score);
    k_gemm<<<dim3(Sn / TM, Hn / TN, Bn), 256, GEMM_SMEM>>>(enc, Wk, V, score);
    k_softmax<<<Bn, 256>>>(score);
    k_wenc<<<dim3(En / 512, Sn / 128, Bn), 128>>>(enc);
    k_hidden<<<dim3(Hn / 128, Bn), 128>>>(Wk, hid);
}

// round 4
// speedup vs baseline: 2.7025x; 1.3286x over previous
#include <cuda_runtime.h>
#include <cuda_fp16.h>
#include <cstdint>

// Problem dims (fixed by the reference)
#define Bn 32
#define Sn 2048
#define En 1024
#define Hn 1024

// ---------------------------------------------------------------------------
// Scratch (allocation-free rule: __device__ globals)
// ---------------------------------------------------------------------------
__device__ float g_wq[Bn * Hn];      // W_q(dec_hidden)  [B,H]
__device__ float g_alpha[Bn * Sn];   // softmax(score)   [B,S]
__device__ float g_u[Bn * En];       // enc^T * alpha    [B,E]

// ---------------------------------------------------------------------------
// Helpers
// ---------------------------------------------------------------------------
// m16n8k16 fp16 mma, D += A*B (row.col), fp32 accumulate. sm_80 baseline PTX.
__device__ __forceinline__ void mma_f16(float* d, uint32_t a0, uint32_t a1,
                                        uint32_t a2, uint32_t a3,
                                        uint32_t b0, uint32_t b1) {
    asm volatile(
        "mma.sync.aligned.m16n8k16.row.col.f32.f16.f16.f32 "
        "{%0,%1,%2,%3}, {%4,%5,%6,%7}, {%8,%9}, {%0,%1,%2,%3};"
        : "+f"(d[0]), "+f"(d[1]), "+f"(d[2]), "+f"(d[3])
        : "r"(a0), "r"(a1), "r"(a2), "r"(a3), "r"(b0), "r"(b1));
}

// Accurate fast tanh: 1 - 2/(exp(2x)+1). abs err ~2e-6, 2 MUFU.
__device__ __forceinline__ float tanh_fast(float x) {
    float e = __expf(2.0f * x);
    return 1.0f - __fdividef(2.0f, e + 1.0f);
}

// Split two floats into (hi, lo) fp16 pairs, packed as half2.
__device__ __forceinline__ void h2_split(float x, float y, uint32_t& h, uint32_t& l) {
    __half2 hh = __floats2half2_rn(x, y);
    float2 hf = __half22float2(hh);
    __half2 ll = __floats2half2_rn(x - hf.x, y - hf.y);
    h = *(uint32_t*)&hh;
    l = *(uint32_t*)&ll;
}

// ---------------------------------------------------------------------------
// Kernel 1: wq[b,h] = dec[b,:] . W_q[h,:]   + zero the score output region
// grid (Hn/128, Bn), 128 threads
// ---------------------------------------------------------------------------
__global__ void k_wq(const float* __restrict__ dec,
                     const float* __restrict__ Wq,
                     float* __restrict__ score_out) {
    __shared__ float ds[En];
    const int b  = blockIdx.y;
    const int h0 = blockIdx.x * 128;
    const int tid = threadIdx.x;

    #pragma unroll
    for (int e = tid * 4; e < En; e += 512)
        *(float4*)&ds[e] = *(const float4*)&dec[b * En + e];

    float2 z = make_float2(0.f, 0.f);
    *(float2*)&score_out[b * Sn + blockIdx.x * 256 + tid * 2] = z;

    __syncthreads();

    const int h = h0 + tid;
    const float* w = Wq + (size_t)h * En;
    float acc = 0.f;
    #pragma unroll 4
    for (int e = 0; e < En; e += 4) {
        float4 w4 = *(const float4*)&w[e];
        acc += w4.x * ds[e] + w4.y * ds[e + 1] + w4.z * ds[e + 2] + w4.w * ds[e + 3];
    }
    g_wq[b * Hn + h] = acc;
}

// ---------------------------------------------------------------------------
// Kernel 2: fp16x3 GEMM (mma.sync m16n8k16) + fused tanh/V epilogue.
//   ctx[s,h] = enc[b,s,:] . Wk[h,:]
//   enc -> hi/lo fp16; Wk*1024 -> hi/lo fp16 (residuals stay normal-range);
//   3 mma passes (hh, hl, lh); epilogue multiplies by 1/1024.
//   score[b,s] += sum_h V[h] * tanh(ctx + wq[b,h])
// Tile 128(s) x 128(h) x 32(k). 256 threads = 8 warps (4m x 2n), warp 32x64.
// SMEM k-order permuted so each fragment (pair) is one LDS.64:
//   within a 16-k group, k -> pos {0,1,4,5,8,9,12,13,2,3,6,7,10,11,14,15}
//   i.e. pos 4t..4t+3 hold k = {2t, 2t+1, 2t+8, 2t+9}.
// grid (Sn/128=16, Hn/128=8, Bn=32)
// ---------------------------------------------------------------------------
#define TM 128
#define TN 128
#define TK 32
#define ROWH 36         // halfs per smem row (32 data + 4 pad, 72B)

__global__ void __launch_bounds__(256, 1)
k_gemm(const float* __restrict__ enc,
       const float* __restrict__ Wk,
       const float* __restrict__ Vv,
       float* __restrict__ score) {
    extern __shared__ __half smh[];
    __half* Ah = smh;                    // [128][ROWH]
    __half* Al = Ah + TM * ROWH;
    __half* Bh = Al + TM * ROWH;
    __half* Bl = Bh + TN * ROWH;
    float* sV   = (float*)(Bl + TN * ROWH);   // [128]
    float* sW   = sV + TN;                    // [128]
    float* sred = sW + TN;                    // [128][2]

    const int tid = threadIdx.x;
    const int wid = tid >> 5;
    const int lane = tid & 31;
    const int g   = lane >> 2;         // 0..7
    const int tig = lane & 3;          // 0..3
    const int wm  = wid >> 1;          // 0..3  (m: 32 rows each)
    const int wn  = wid & 1;           // 0..1  (n: 64 cols each)

    const int s0 = blockIdx.x * TM;
    const int h0 = blockIdx.y * TN;
    const int b  = blockIdx.z;

    // Stage V and wq tiles
    if (tid < TN) {
        sV[tid] = Vv[h0 + tid];
        sW[tid] = g_wq[b * Hn + h0 + tid];
    }

    // Global load mapping: row = tid/2 (0..127), k-base = (tid&1)*16
    const int row = tid >> 1;
    const int cb  = (tid & 1) * 16;
    const float* aPtr = enc + ((size_t)(b * Sn + s0 + row)) * En + cb;
    const float* bPtr = Wk  + ((size_t)(h0 + row)) * En + cb;

    float acc[2][8][4];
    #pragma unroll
    for (int mt = 0; mt < 2; mt++)
        #pragma unroll
        for (int nt = 0; nt < 8; nt++)
            #pragma unroll
            for (int r = 0; r < 4; r++) acc[mt][nt][r] = 0.f;

    // Prologue LDG of chunk 0
    float4 ar[4], br[4];
    #pragma unroll
    for (int i = 0; i < 4; i++) {
        ar[i] = *(const float4*)(aPtr + i * 4);
        br[i] = *(const float4*)(bPtr + i * 4);
    }

    const int sbase = row * ROWH + cb;    // halfs
    const int NCHUNK = En / TK;           // 32

    for (int c = 0; c < NCHUNK; c++) {
        // Convert + STS current chunk (permuted k layout).
        // f-index groups per STS.64 j: {2j, 2j+1, 2j+8, 2j+9} -> pos 4j.
        // f0..f7 = ar[0..1], f8..f15 = ar[2..3].
        {
            const float* fa = &ar[0].x;
            const float* fb = &br[0].x;
            #pragma unroll
            for (int j = 0; j < 4; j++) {
                uint32_t h01, l01, h89, l89;
                h2_split(fa[2 * j], fa[2 * j + 1], h01, l01);
                h2_split(fa[2 * j + 8], fa[2 * j + 9], h89, l89);
                *(uint2*)&Ah[sbase + 4 * j] = make_uint2(h01, h89);
                *(uint2*)&Al[sbase + 4 * j] = make_uint2(l01, l89);
                // W scaled by 1024 so fp16 residuals stay in normal range
                h2_split(fb[2 * j] * 1024.f, fb[2 * j + 1] * 1024.f, h01, l01);
                h2_split(fb[2 * j + 8] * 1024.f, fb[2 * j + 9] * 1024.f, h89, l89);
                *(uint2*)&Bh[sbase + 4 * j] = make_uint2(h01, h89);
                *(uint2*)&Bl[sbase + 4 * j] = make_uint2(l01, l89);
            }
        }
        __syncthreads();

        // Prefetch next chunk (overlaps with mma below)
        if (c + 1 < NCHUNK) {
            const int k0 = (c + 1) * TK;
            #pragma unroll
            for (int i = 0; i < 4; i++) {
                ar[i] = *(const float4*)(aPtr + k0 + i * 4);
                br[i] = *(const float4*)(bPtr + k0 + i * 4);
            }
        }

        // Compute: 2 k-steps of 16
        #pragma unroll
        for (int ks = 0; ks < 2; ks++) {
            const int ko = ks * 16 + 4 * tig;
            // B fragments: (b0,b1) in one LDS.64
            uint2 bHf[8], bLf[8];
            #pragma unroll
            for (int nt = 0; nt < 8; nt++) {
                const int nr = wn * 64 + nt * 8 + g;
                bHf[nt] = *(uint2*)&Bh[nr * ROWH + ko];
                bLf[nt] = *(uint2*)&Bl[nr * ROWH + ko];
            }
            #pragma unroll
            for (int mt = 0; mt < 2; mt++) {
                const int mr = wm * 32 + mt * 16;
                // A fragments: (a0,a2) rows g; (a1,a3) rows g+8
                uint2 aH02 = *(uint2*)&Ah[(mr + g)     * ROWH + ko];
                uint2 aH13 = *(uint2*)&Ah[(mr + g + 8) * ROWH + ko];
                uint2 aL02 = *(uint2*)&Al[(mr + g)     * ROWH + ko];
                uint2 aL13 = *(uint2*)&Al[(mr + g + 8) * ROWH + ko];
                #pragma unroll
                for (int nt = 0; nt < 8; nt++) {
                    mma_f16(acc[mt][nt], aH02.x, aH13.x, aH02.y, aH13.y,
                            bHf[nt].x, bHf[nt].y);                       // hi*hi
                    mma_f16(acc[mt][nt], aH02.x, aH13.x, aH02.y, aH13.y,
                            bLf[nt].x, bLf[nt].y);                       // hi*lo
                    mma_f16(acc[mt][nt], aL02.x, aL13.x, aL02.y, aL13.y,
                            bHf[nt].x, bHf[nt].y);                       // lo*hi
                }
            }
        }
        __syncthreads();
    }

    // ---- Epilogue: score[b, s] += sum_h V[h]*tanh(ctx/1024 + wq[h]) ----
    // acc fragment: c0,c1 = (row g, cols 2tig,2tig+1); c2,c3 = (row g+8, same cols)
    const float inv_sc = 1.0f / 1024.0f;
    float p[4] = {0.f, 0.f, 0.f, 0.f};
    #pragma unroll
    for (int mt = 0; mt < 2; mt++)
        #pragma unroll
        for (int nt = 0; nt < 8; nt++) {
            const int hl = wn * 64 + nt * 8 + 2 * tig;
            const float v0 = sV[hl], v1 = sV[hl + 1];
            const float w0 = sW[hl], w1 = sW[hl + 1];
            p[mt * 2 + 0] += v0 * tanh_fast(acc[mt][nt][0] * inv_sc + w0)
                           + v1 * tanh_fast(acc[mt][nt][1] * inv_sc + w1);
            p[mt * 2 + 1] += v0 * tanh_fast(acc[mt][nt][2] * inv_sc + w0)
                           + v1 * tanh_fast(acc[mt][nt][3] * inv_sc + w1);
        }
    // quad reduce (lane = g*4 + tig)
    #pragma unroll
    for (int o = 1; o < 4; o <<= 1) {
        #pragma unroll
        for (int i = 0; i < 4; i++)
            p[i] += __shfl_xor_sync(0xFFFFFFFFu, p[i], o);
    }
    if (tig == 0) {
        #pragma unroll
        for (int mt = 0; mt < 2; mt++)
            #pragma unroll
            for (int hf = 0; hf < 2; hf++) {
                const int r = wm * 32 + mt * 16 + hf * 8 + g;
                sred[r * 2 + wn] = p[mt * 2 + hf];
            }
    }
    __syncthreads();
    if (tid < TM)
        atomicAdd(&score[b * Sn + s0 + tid], sred[tid * 2] + sred[tid * 2 + 1]);
}

#define GEMM_SMEM (4 * TM * ROWH * 2 + (2 * TN + 2 * TM) * 4)   // 38912 B

// ---------------------------------------------------------------------------
// Kernel 3: per-batch softmax over S -> g_alpha; also zero g_u.
// ---------------------------------------------------------------------------
__global__ void k_softmax(const float* __restrict__ score) {
    __shared__ float sh[256];
    const int b = blockIdx.x;
    const int tid = threadIdx.x;

    float vals[8];
    float lmax = -3.4e38f;
    #pragma unroll
    for (int i = 0; i < 8; i++) {
        vals[i] = score[b * Sn + tid + i * 256];
        lmax = fmaxf(lmax, vals[i]);
    }
    sh[tid] = lmax;
    __syncthreads();
    for (int off = 128; off > 0; off >>= 1) {
        if (tid < off) sh[tid] = fmaxf(sh[tid], sh[tid + off]);
        __syncthreads();
    }
    const float m = sh[0];
    __syncthreads();

    float lsum = 0.f;
    #pragma unroll
    for (int i = 0; i < 8; i++) {
        vals[i] = __expf(vals[i] - m);
        lsum += vals[i];
    }
    sh[tid] = lsum;
    __syncthreads();
    for (int off = 128; off > 0; off >>= 1) {
        if (tid < off) sh[tid] += sh[tid + off];
        __syncthreads();
    }
    const float inv = 1.0f / sh[0];
    #pragma unroll
    for (int i = 0; i < 8; i++)
        g_alpha[b * Sn + tid + i * 256] = vals[i] * inv;

    for (int e = tid; e < En; e += 256) g_u[b * En + e] = 0.f;
}

// ---------------------------------------------------------------------------
// Kernel 4: u[b,e] = sum_s alpha[b,s] * enc[b,s,e]
// grid (En/512, Sn/64, Bn), 128 threads (s-chunk 64 for more MLP)
// ---------------------------------------------------------------------------
__global__ void k_wenc(const float* __restrict__ enc) {
    const int b  = blockIdx.z;
    const int sc = blockIdx.y * 64;
    const int e0 = blockIdx.x * 512 + threadIdx.x * 4;

    const float* ep = enc + ((size_t)b * Sn + sc) * En + e0;
    const float* ap = g_alpha + b * Sn + sc;

    float4 acc = make_float4(0.f, 0.f, 0.f, 0.f);
    #pragma unroll 4
    for (int s = 0; s < 64; s++) {
        float a = ap[s];
        float4 v = *(const float4*)(ep + (size_t)s * En);
        acc.x += a * v.x; acc.y += a * v.y;
        acc.z += a * v.z; acc.w += a * v.w;
    }
    atomicAdd(&g_u[b * En + e0 + 0], acc.x);
    atomicAdd(&g_u[b * En + e0 + 1], acc.y);
    atomicAdd(&g_u[b * En + e0 + 2], acc.z);
    atomicAdd(&g_u[b * En + e0 + 3], acc.w);
}

// ---------------------------------------------------------------------------
// Kernel 5: hidden[b,h] = W_k[h,:] . u[b,:]
// ---------------------------------------------------------------------------
__global__ void k_hidden(const float* __restrict__ Wk, float* __restrict__ hid) {
    __shared__ float us[En];
    const int b = blockIdx.y;
    const int h = blockIdx.x * 128 + threadIdx.x;

    #pragma unroll
    for (int e = threadIdx.x * 4; e < En; e += 512)
        *(float4*)&us[e] = *(const float4*)&g_u[b * En + e];
    __syncthreads();

    const float* w = Wk + (size_t)h * En;
    float acc = 0.f;
    #pragma unroll 4
    for (int e = 0; e < En; e += 4) {
        float4 w4 = *(const float4*)&w[e];
        acc += w4.x * us[e] + w4.y * us[e + 1] + w4.z * us[e + 2] + w4.w * us[e + 3];
    }
    hid[b * Hn + h] = acc;
}

// ---------------------------------------------------------------------------
// Launch: 5 ordered kernels, default stream. Graph-capturable, allocation-free.
// Output layout: [ hidden_state (B*H) | score (B*S) ]
// ---------------------------------------------------------------------------
extern "C" void kernel_launch(void* const* d_in, const int* in_sizes, int n_in,
                              void* d_out, int out_size) {
    const float* enc = (const float*)d_in[0];   // [B,S,E]
    const float* dec = (const float*)d_in[1];   // [B,E]
    const float* Wk  = (const float*)d_in[2];   // [H,E]
    const float* Wq  = (const float*)d_in[3];   // [H,E]
    const float* V   = (const float*)d_in[4];   // [H]

    float* out   = (float*)d_out;
    float* hid   = out;              // B*H
    float* score = out + Bn * Hn;    // B*S

    k_wq<<<dim3(Hn / 128, Bn), 128>>>(dec, Wq, score);
    k_gemm<<<dim3(Sn / TM, Hn / TN, Bn), 256, GEMM_SMEM>>>(enc, Wk, V, score);
    k_softmax<<<Bn, 256>>>(score);
    k_wenc<<<dim3(En / 512, Sn / 64, Bn), 128>>>(enc);
    k_hidden<<<dim3(Hn / 128, Bn), 128>>>(Wk, hid);
}

// round 5
// speedup vs baseline: 2.8749x; 1.0638x over previous
#include <cuda_runtime.h>
#include <cuda_fp16.h>
#include <cstdint>

// Problem dims (fixed by the reference)
#define Bn 32
#define Sn 2048
#define En 1024
#define Hn 1024

// ---------------------------------------------------------------------------
// Scratch (allocation-free rule: __device__ globals)
// ---------------------------------------------------------------------------
__device__ float g_wq[Bn * Hn];      // W_q(dec_hidden)  [B,H]
__device__ float g_alpha[Bn * Sn];   // softmax(score)   [B,S]
__device__ float g_u[Bn * En];       // enc^T * alpha    [B,E]
// fp16 hi/lo splits, k-permuted within each 16-group:
//   pos 4t..4t+3  <-  k { 2t, 2t+1, 2t+8, 2t+9 }
__device__ __align__(16) __half g_ench[(size_t)Bn * Sn * En];
__device__ __align__(16) __half g_encl[(size_t)Bn * Sn * En];
__device__ __align__(16) __half g_wkh[Hn * En];   // W_k * 1024
__device__ __align__(16) __half g_wkl[Hn * En];

// ---------------------------------------------------------------------------
// Helpers
// ---------------------------------------------------------------------------
__device__ __forceinline__ uint32_t smem_u32(const void* p) {
    uint32_t a;
    asm("{ .reg .u64 t; cvta.to.shared.u64 t, %1; cvt.u32.u64 %0, t; }" : "=r"(a) : "l"(p));
    return a;
}

// m16n8k16 fp16 mma, D += A*B (row.col), fp32 accumulate. sm_80 baseline PTX.
__device__ __forceinline__ void mma_f16(float* d, uint32_t a0, uint32_t a1,
                                        uint32_t a2, uint32_t a3,
                                        uint32_t b0, uint32_t b1) {
    asm volatile(
        "mma.sync.aligned.m16n8k16.row.col.f32.f16.f16.f32 "
        "{%0,%1,%2,%3}, {%4,%5,%6,%7}, {%8,%9}, {%0,%1,%2,%3};"
        : "+f"(d[0]), "+f"(d[1]), "+f"(d[2]), "+f"(d[3])
        : "r"(a0), "r"(a1), "r"(a2), "r"(a3), "r"(b0), "r"(b1));
}

#define CP_ASYNC8(dst, src) \
    asm volatile("cp.async.ca.shared.global [%0], [%1], 8;" \
        :: "r"(dst), "l"(src) : "memory")
#define CP_COMMIT() asm volatile("cp.async.commit_group;" ::: "memory")
#define CP_WAIT0()  asm volatile("cp.async.wait_group 0;" ::: "memory")

// Accurate fast tanh: 1 - 2/(exp(2x)+1). abs err ~2e-6, 2 MUFU.
__device__ __forceinline__ float tanh_fast(float x) {
    float e = __expf(2.0f * x);
    return 1.0f - __fdividef(2.0f, e + 1.0f);
}

// Split two floats into (hi, lo) fp16 pairs, packed as half2.
__device__ __forceinline__ void h2_split(float x, float y, uint32_t& h, uint32_t& l) {
    __half2 hh = __floats2half2_rn(x, y);
    float2 hf = __half22float2(hh);
    __half2 ll = __floats2half2_rn(x - hf.x, y - hf.y);
    h = *(uint32_t*)&hh;
    l = *(uint32_t*)&ll;
}

// ---------------------------------------------------------------------------
// Kernel 0: fp32 -> (hi, lo) fp16, k-permuted in 16-groups, optional scale.
// One thread per 16-element group. Coalesced 64B reads, 32B writes x2.
// ---------------------------------------------------------------------------
__global__ void k_prep(const float* __restrict__ src, __half* __restrict__ dh,
                       __half* __restrict__ dl, int ngroups, float scale) {
    int gid = blockIdx.x * blockDim.x + threadIdx.x;
    if (gid >= ngroups) return;
    float f[16];
    const float4* s = (const float4*)(src + (size_t)gid * 16);
    *(float4*)&f[0]  = s[0];
    *(float4*)&f[4]  = s[1];
    *(float4*)&f[8]  = s[2];
    *(float4*)&f[12] = s[3];
    uint32_t oh[8], ol[8];
    #pragma unroll
    for (int t = 0; t < 4; t++) {
        h2_split(f[2 * t] * scale,     f[2 * t + 1] * scale, oh[2 * t],     ol[2 * t]);
        h2_split(f[2 * t + 8] * scale, f[2 * t + 9] * scale, oh[2 * t + 1], ol[2 * t + 1]);
    }
    uint4* ph = (uint4*)(dh + (size_t)gid * 16);
    uint4* pl = (uint4*)(dl + (size_t)gid * 16);
    ph[0] = make_uint4(oh[0], oh[1], oh[2], oh[3]);
    ph[1] = make_uint4(oh[4], oh[5], oh[6], oh[7]);
    pl[0] = make_uint4(ol[0], ol[1], ol[2], ol[3]);
    pl[1] = make_uint4(ol[4], ol[5], ol[6], ol[7]);
}

// ---------------------------------------------------------------------------
// Kernel 1: wq[b,h] = dec[b,:] . W_q[h,:]   + zero the score output region
// grid (Hn/128, Bn), 128 threads
// ---------------------------------------------------------------------------
__global__ void k_wq(const float* __restrict__ dec,
                     const float* __restrict__ Wq,
                     float* __restrict__ score_out) {
    __shared__ float ds[En];
    const int b  = blockIdx.y;
    const int h0 = blockIdx.x * 128;
    const int tid = threadIdx.x;

    #pragma unroll
    for (int e = tid * 4; e < En; e += 512)
        *(float4*)&ds[e] = *(const float4*)&dec[b * En + e];

    float2 z = make_float2(0.f, 0.f);
    *(float2*)&score_out[b * Sn + blockIdx.x * 256 + tid * 2] = z;

    __syncthreads();

    const int h = h0 + tid;
    const float* w = Wq + (size_t)h * En;
    float acc = 0.f;
    #pragma unroll 4
    for (int e = 0; e < En; e += 4) {
        float4 w4 = *(const float4*)&w[e];
        acc += w4.x * ds[e] + w4.y * ds[e + 1] + w4.z * ds[e + 2] + w4.w * ds[e + 3];
    }
    g_wq[b * Hn + h] = acc;
}

// ---------------------------------------------------------------------------
// Kernel 2: fp16x3 GEMM (mma.sync m16n8k16) + fused tanh/V epilogue.
// Operands preconverted (k_prep). Main loop = cp.async + mma only,
// 2-stage double buffer, one __syncthreads per chunk.
// Tile 128(s) x 128(h) x 32(k). 256 threads = 8 warps (4m x 2n), warp 32x64.
// grid (Sn/128=16, Hn/128=8, Bn=32)
// ---------------------------------------------------------------------------
#define TM 128
#define TN 128
#define TK 32
#define ROWH 36                       // halfs per smem row (32 data + 4 pad, 72B)
#define ARR_HALFS (TM * ROWH)         // 4608 halfs per operand array
#define STAGE_HALFS (4 * ARR_HALFS)   // 18432 halfs = 36864 B per stage
#define STAGE_BYTES (STAGE_HALFS * 2)

__global__ void __launch_bounds__(256)
k_gemm(const float* __restrict__ Vv, float* __restrict__ score) {
    extern __shared__ __half smh[];
    float* sV   = (float*)(smh + 2 * STAGE_HALFS);   // [128]
    float* sW   = sV + TN;                           // [128]
    float* sred = sW + TN;                           // [128][2]

    const int tid = threadIdx.x;
    const int wid = tid >> 5;
    const int lane = tid & 31;
    const int g   = lane >> 2;         // 0..7
    const int tig = lane & 3;          // 0..3
    const int wm  = wid >> 1;          // 0..3  (m: 32 rows each)
    const int wn  = wid & 1;           // 0..1  (n: 64 cols each)

    const int s0 = blockIdx.x * TM;
    const int h0 = blockIdx.y * TN;
    const int b  = blockIdx.z;

    // Stage V and wq tiles
    if (tid < TN) {
        sV[tid] = Vv[h0 + tid];
        sW[tid] = g_wq[b * Hn + h0 + tid];
    }

    // cp.async task mapping: 4 tasks/thread/array, 8B each.
    // task = tid + 256*it -> row = task>>3 (0..127), seg = task&7 (8B units)
    const uint32_t smb = smem_u32(smh);
    size_t aOff[4], bOff[4];
    uint32_t sOff[4];
    #pragma unroll
    for (int it = 0; it < 4; it++) {
        const int task = tid + 256 * it;
        const int trow = task >> 3;
        const int tseg = task & 7;
        aOff[it] = ((size_t)(b * Sn + s0 + trow)) * En + tseg * 4;  // halfs
        bOff[it] = ((size_t)(h0 + trow)) * En + tseg * 4;
        sOff[it] = trow * (ROWH * 2) + tseg * 8;                    // bytes
    }

    float acc[2][8][4];
    #pragma unroll
    for (int mt = 0; mt < 2; mt++)
        #pragma unroll
        for (int nt = 0; nt < 8; nt++)
            #pragma unroll
            for (int r = 0; r < 4; r++) acc[mt][nt][r] = 0.f;

    const int NCHUNK = En / TK;   // 32

    // Issue one chunk's 16 cp.asyncs (4 arrays x 4 tasks)
    auto issue = [&](int c, int st) {
        const uint32_t base = smb + st * STAGE_BYTES;
        const size_t ck = (size_t)c * TK;   // halfs
        #pragma unroll
        for (int it = 0; it < 4; it++) {
            CP_ASYNC8(base + sOff[it],                      (const char*)&g_ench[aOff[it] + ck]);
            CP_ASYNC8(base + ARR_HALFS * 2 + sOff[it],      (const char*)&g_encl[aOff[it] + ck]);
            CP_ASYNC8(base + ARR_HALFS * 4 + sOff[it],      (const char*)&g_wkh[bOff[it] + ck]);
            CP_ASYNC8(base + ARR_HALFS * 6 + sOff[it],      (const char*)&g_wkl[bOff[it] + ck]);
        }
    };

    issue(0, 0);
    CP_COMMIT();

    for (int c = 0; c < NCHUNK; c++) {
        const int st = c & 1;
        CP_WAIT0();
        __syncthreads();           // stage st ready; stage st^1 free everywhere
        if (c + 1 < NCHUNK) {
            issue(c + 1, st ^ 1);
            CP_COMMIT();
        }

        const __half* Ah = smh + st * STAGE_HALFS;
        const __half* Al = Ah + ARR_HALFS;
        const __half* Bh = Al + ARR_HALFS;
        const __half* Bl = Bh + ARR_HALFS;

        #pragma unroll
        for (int ks = 0; ks < 2; ks++) {
            const int ko = ks * 16 + 4 * tig;
            uint2 bHf[8], bLf[8];
            #pragma unroll
            for (int nt = 0; nt < 8; nt++) {
                const int nr = wn * 64 + nt * 8 + g;
                bHf[nt] = *(uint2*)&Bh[nr * ROWH + ko];
                bLf[nt] = *(uint2*)&Bl[nr * ROWH + ko];
            }
            #pragma unroll
            for (int mt = 0; mt < 2; mt++) {
                const int mr = wm * 32 + mt * 16;
                uint2 aH02 = *(uint2*)&Ah[(mr + g)     * ROWH + ko];
                uint2 aH13 = *(uint2*)&Ah[(mr + g + 8) * ROWH + ko];
                uint2 aL02 = *(uint2*)&Al[(mr + g)     * ROWH + ko];
                uint2 aL13 = *(uint2*)&Al[(mr + g + 8) * ROWH + ko];
                #pragma unroll
                for (int nt = 0; nt < 8; nt++) {
                    mma_f16(acc[mt][nt], aH02.x, aH13.x, aH02.y, aH13.y,
                            bHf[nt].x, bHf[nt].y);                       // hi*hi
                    mma_f16(acc[mt][nt], aH02.x, aH13.x, aH02.y, aH13.y,
                            bLf[nt].x, bLf[nt].y);                       // hi*lo
                    mma_f16(acc[mt][nt], aL02.x, aL13.x, aL02.y, aL13.y,
                            bHf[nt].x, bHf[nt].y);                       // lo*hi
                }
            }
        }
        __syncthreads();           // all warps done with stage st before overwrite
    }

    // ---- Epilogue: score[b, s] += sum_h V[h]*tanh(ctx/1024 + wq[h]) ----
    const float inv_sc = 1.0f / 1024.0f;
    float p[4] = {0.f, 0.f, 0.f, 0.f};
    #pragma unroll
    for (int mt = 0; mt < 2; mt++)
        #pragma unroll
        for (int nt = 0; nt < 8; nt++) {
            const int hl = wn * 64 + nt * 8 + 2 * tig;
            const float v0 = sV[hl], v1 = sV[hl + 1];
            const float w0 = sW[hl], w1 = sW[hl + 1];
            p[mt * 2 + 0] += v0 * tanh_fast(acc[mt][nt][0] * inv_sc + w0)
                           + v1 * tanh_fast(acc[mt][nt][1] * inv_sc + w1);
            p[mt * 2 + 1] += v0 * tanh_fast(acc[mt][nt][2] * inv_sc + w0)
                           + v1 * tanh_fast(acc[mt][nt][3] * inv_sc + w1);
        }
    #pragma unroll
    for (int o = 1; o < 4; o <<= 1) {
        #pragma unroll
        for (int i = 0; i < 4; i++)
            p[i] += __shfl_xor_sync(0xFFFFFFFFu, p[i], o);
    }
    if (tig == 0) {
        #pragma unroll
        for (int mt = 0; mt < 2; mt++)
            #pragma unroll
            for (int hf = 0; hf < 2; hf++) {
                const int r = wm * 32 + mt * 16 + hf * 8 + g;
                sred[r * 2 + wn] = p[mt * 2 + hf];
            }
    }
    __syncthreads();
    if (tid < TM)
        atomicAdd(&score[b * Sn + s0 + tid], sred[tid * 2] + sred[tid * 2 + 1]);
}

#define GEMM_SMEM (2 * STAGE_BYTES + (2 * TN + 2 * TM) * 4)   // 75776 B

// ---------------------------------------------------------------------------
// Kernel 3: per-batch softmax over S -> g_alpha; also zero g_u.
// ---------------------------------------------------------------------------
__global__ void k_softmax(const float* __restrict__ score) {
    __shared__ float sh[256];
    const int b = blockIdx.x;
    const int tid = threadIdx.x;

    float vals[8];
    float lmax = -3.4e38f;
    #pragma unroll
    for (int i = 0; i < 8; i++) {
        vals[i] = score[b * Sn + tid + i * 256];
        lmax = fmaxf(lmax, vals[i]);
    }
    sh[tid] = lmax;
    __syncthreads();
    for (int off = 128; off > 0; off >>= 1) {
        if (tid < off) sh[tid] = fmaxf(sh[tid], sh[tid + off]);
        __syncthreads();
    }
    const float m = sh[0];
    __syncthreads();

    float lsum = 0.f;
    #pragma unroll
    for (int i = 0; i < 8; i++) {
        vals[i] = __expf(vals[i] - m);
        lsum += vals[i];
    }
    sh[tid] = lsum;
    __syncthreads();
    for (int off = 128; off > 0; off >>= 1) {
        if (tid < off) sh[tid] += sh[tid + off];
        __syncthreads();
    }
    const float inv = 1.0f / sh[0];
    #pragma unroll
    for (int i = 0; i < 8; i++)
        g_alpha[b * Sn + tid + i * 256] = vals[i] * inv;

    for (int e = tid; e < En; e += 256) g_u[b * En + e] = 0.f;
}

// ---------------------------------------------------------------------------
// Kernel 4: u[b,e] = sum_s alpha[b,s] * enc[b,s,e]
// grid (En/512, Sn/64, Bn), 128 threads
// ---------------------------------------------------------------------------
__global__ void k_wenc(const float* __restrict__ enc) {
    const int b  = blockIdx.z;
    const int sc = blockIdx.y * 64;
    const int e0 = blockIdx.x * 512 + threadIdx.x * 4;

    const float* ep = enc + ((size_t)b * Sn + sc) * En + e0;
    const float* ap = g_alpha + b * Sn + sc;

    float4 acc = make_float4(0.f, 0.f, 0.f, 0.f);
    #pragma unroll 4
    for (int s = 0; s < 64; s++) {
        float a = ap[s];
        float4 v = *(const float4*)(ep + (size_t)s * En);
        acc.x += a * v.x; acc.y += a * v.y;
        acc.z += a * v.z; acc.w += a * v.w;
    }
    atomicAdd(&g_u[b * En + e0 + 0], acc.x);
    atomicAdd(&g_u[b * En + e0 + 1], acc.y);
    atomicAdd(&g_u[b * En + e0 + 2], acc.z);
    atomicAdd(&g_u[b * En + e0 + 3], acc.w);
}

// ---------------------------------------------------------------------------
// Kernel 5: hidden[b,h] = W_k[h,:] . u[b,:]
// ---------------------------------------------------------------------------
__global__ void k_hidden(const float* __restrict__ Wk, float* __restrict__ hid) {
    __shared__ float us[En];
    const int b = blockIdx.y;
    const int h = blockIdx.x * 128 + threadIdx.x;

    #pragma unroll
    for (int e = threadIdx.x * 4; e < En; e += 512)
        *(float4*)&us[e] = *(const float4*)&g_u[b * En + e];
    __syncthreads();

    const float* w = Wk + (size_t)h * En;
    float acc = 0.f;
    #pragma unroll 4
    for (int e = 0; e < En; e += 4) {
        float4 w4 = *(const float4*)&w[e];
        acc += w4.x * us[e] + w4.y * us[e + 1] + w4.z * us[e + 2] + w4.w * us[e + 3];
    }
    hid[b * Hn + h] = acc;
}

// ---------------------------------------------------------------------------
// Launch. Graph-capturable, allocation-free.
// Output layout: [ hidden_state (B*H) | score (B*S) ]
// ---------------------------------------------------------------------------
extern "C" void kernel_launch(void* const* d_in, const int* in_sizes, int n_in,
                              void* d_out, int out_size) {
    const float* enc = (const float*)d_in[0];   // [B,S,E]
    const float* dec = (const float*)d_in[1];   // [B,E]
    const float* Wk  = (const float*)d_in[2];   // [H,E]
    const float* Wq  = (const float*)d_in[3];   // [H,E]
    const float* V   = (const float*)d_in[4];   // [H]

    float* out   = (float*)d_out;
    float* hid   = out;              // B*H
    float* score = out + Bn * Hn;    // B*S

    static bool attr_set = false;
    if (!attr_set) {
        cudaFuncSetAttribute(k_gemm, cudaFuncAttributeMaxDynamicSharedMemorySize,
                             GEMM_SMEM);
        attr_set = true;
    }

    void *ench, *encl, *wkh, *wkl;
    cudaGetSymbolAddress(&ench, g_ench);
    cudaGetSymbolAddress(&encl, g_encl);
    cudaGetSymbolAddress(&wkh,  g_wkh);
    cudaGetSymbolAddress(&wkl,  g_wkl);

    const int encGroups = Bn * Sn * En / 16;   // 4,194,304
    const int wkGroups  = Hn * En / 16;        // 65,536
    k_prep<<<encGroups / 256, 256>>>(enc, (__half*)ench, (__half*)encl, encGroups, 1.0f);
    k_prep<<<wkGroups / 256, 256>>>(Wk, (__half*)wkh, (__half*)wkl, wkGroups, 1024.0f);

    k_wq<<<dim3(Hn / 128, Bn), 128>>>(dec, Wq, score);
    k_gemm<<<dim3(Sn / TM, Hn / TN, Bn), 256, GEMM_SMEM>>>(V, score);
    k_softmax<<<Bn, 256>>>(score);
    k_wenc<<<dim3(En / 512, Sn / 64, Bn), 128>>>(enc);
    k_hidden<<<dim3(Hn / 128, Bn), 128>>>(Wk, hid);
}

// round 6
// speedup vs baseline: 3.4557x; 1.2020x over previous
#include <cuda_runtime.h>
#include <cuda_fp16.h>
#include <cstdint>

// Problem dims (fixed by the reference)
#define Bn 32
#define Sn 2048
#define En 1024
#define Hn 1024

// ---------------------------------------------------------------------------
// Scratch (allocation-free rule: __device__ globals)
// ---------------------------------------------------------------------------
__device__ float g_wq[Bn * Hn];      // W_q(dec_hidden)  [B,H]
__device__ float g_alpha[Bn * Sn];   // softmax(score)   [B,S]
__device__ float g_u[Bn * En];       // enc^T * alpha    [B,E]
// fp16 hi/lo splits, canonical layout (k contiguous per row)
__device__ __align__(16) __half g_ench[(size_t)Bn * Sn * En];
__device__ __align__(16) __half g_encl[(size_t)Bn * Sn * En];
__device__ __align__(16) __half g_wkh[Hn * En];   // W_k * 1024
__device__ __align__(16) __half g_wkl[Hn * En];

// ---------------------------------------------------------------------------
// Helpers
// ---------------------------------------------------------------------------
__device__ __forceinline__ uint32_t smem_u32(const void* p) {
    uint32_t a;
    asm("{ .reg .u64 t; cvta.to.shared.u64 t, %1; cvt.u32.u64 %0, t; }" : "=r"(a) : "l"(p));
    return a;
}

// m16n8k16 fp16 mma, D += A*B (row.col), fp32 accumulate. sm_80 baseline PTX.
__device__ __forceinline__ void mma_f16(float* d, const uint32_t* a,
                                        uint32_t b0, uint32_t b1) {
    asm volatile(
        "mma.sync.aligned.m16n8k16.row.col.f32.f16.f16.f32 "
        "{%0,%1,%2,%3}, {%4,%5,%6,%7}, {%8,%9}, {%0,%1,%2,%3};"
        : "+f"(d[0]), "+f"(d[1]), "+f"(d[2]), "+f"(d[3])
        : "r"(a[0]), "r"(a[1]), "r"(a[2]), "r"(a[3]), "r"(b0), "r"(b1));
}

#define LDSM_X4(r, addr)                                                        \
    asm volatile("ldmatrix.sync.aligned.m8n8.x4.shared.b16 {%0,%1,%2,%3}, [%4];" \
        : "=r"((r)[0]), "=r"((r)[1]), "=r"((r)[2]), "=r"((r)[3]) : "r"(addr))

#define CP_ASYNC8(dst, src) \
    asm volatile("cp.async.ca.shared.global [%0], [%1], 8;" \
        :: "r"(dst), "l"(src) : "memory")
#define CP_COMMIT() asm volatile("cp.async.commit_group;" ::: "memory")
#define CP_WAIT0()  asm volatile("cp.async.wait_group 0;" ::: "memory")
#define CP_WAIT1()  asm volatile("cp.async.wait_group 1;" ::: "memory")

// Accurate fast tanh: 1 - 2/(exp(2x)+1). abs err ~2e-6, 2 MUFU.
__device__ __forceinline__ float tanh_fast(float x) {
    float e = __expf(2.0f * x);
    return 1.0f - __fdividef(2.0f, e + 1.0f);
}

// Split two floats into (hi, lo) fp16 pairs, packed as half2.
__device__ __forceinline__ void h2_split(float x, float y, uint32_t& h, uint32_t& l) {
    __half2 hh = __floats2half2_rn(x, y);
    float2 hf = __half22float2(hh);
    __half2 ll = __floats2half2_rn(x - hf.x, y - hf.y);
    h = *(uint32_t*)&hh;
    l = *(uint32_t*)&ll;
}

// ---------------------------------------------------------------------------
// Kernel 0: fp32 -> (hi, lo) fp16, canonical order, optional scale.
// One thread per 16-element group. Coalesced 64B reads, 32B writes x2.
// ---------------------------------------------------------------------------
__global__ void k_prep(const float* __restrict__ src, __half* __restrict__ dh,
                       __half* __restrict__ dl, int ngroups, float scale) {
    int gid = blockIdx.x * blockDim.x + threadIdx.x;
    if (gid >= ngroups) return;
    float f[16];
    const float4* s = (const float4*)(src + (size_t)gid * 16);
    *(float4*)&f[0]  = s[0];
    *(float4*)&f[4]  = s[1];
    *(float4*)&f[8]  = s[2];
    *(float4*)&f[12] = s[3];
    uint32_t oh[8], ol[8];
    #pragma unroll
    for (int t = 0; t < 8; t++)
        h2_split(f[2 * t] * scale, f[2 * t + 1] * scale, oh[t], ol[t]);
    uint4* ph = (uint4*)(dh + (size_t)gid * 16);
    uint4* pl = (uint4*)(dl + (size_t)gid * 16);
    ph[0] = make_uint4(oh[0], oh[1], oh[2], oh[3]);
    ph[1] = make_uint4(oh[4], oh[5], oh[6], oh[7]);
    pl[0] = make_uint4(ol[0], ol[1], ol[2], ol[3]);
    pl[1] = make_uint4(ol[4], ol[5], ol[6], ol[7]);
}

// ---------------------------------------------------------------------------
// Kernel 1: wq[b,h] = dec[b,:] . W_q[h,:]   + zero the score output region
// ---------------------------------------------------------------------------
__global__ void k_wq(const float* __restrict__ dec,
                     const float* __restrict__ Wq,
                     float* __restrict__ score_out) {
    __shared__ float ds[En];
    const int b  = blockIdx.y;
    const int h0 = blockIdx.x * 128;
    const int tid = threadIdx.x;

    #pragma unroll
    for (int e = tid * 4; e < En; e += 512)
        *(float4*)&ds[e] = *(const float4*)&dec[b * En + e];

    float2 z = make_float2(0.f, 0.f);
    *(float2*)&score_out[b * Sn + blockIdx.x * 256 + tid * 2] = z;

    __syncthreads();

    const int h = h0 + tid;
    const float* w = Wq + (size_t)h * En;
    float acc = 0.f;
    #pragma unroll 4
    for (int e = 0; e < En; e += 4) {
        float4 w4 = *(const float4*)&w[e];
        acc += w4.x * ds[e] + w4.y * ds[e + 1] + w4.z * ds[e + 2] + w4.w * ds[e + 3];
    }
    g_wq[b * Hn + h] = acc;
}

// ---------------------------------------------------------------------------
// Kernel 2: fp16x3 GEMM + fused tanh/V epilogue.
// ldmatrix.x4 fragment loads (conflict-free 80B row pitch), cp.async 3-stage
// pipeline, one __syncthreads per chunk.
// Tile 128(s) x 128(h) x 32(k). 256 threads = 8 warps (4m x 2n), warp 32x64.
// grid (Sn/128=16, Hn/128=8, Bn=32)
// ---------------------------------------------------------------------------
#define TM 128
#define TN 128
#define TK 32
#define ROWH 40                        // halfs per smem row (32 data + 8 pad, 80B)
#define ROWB (ROWH * 2)                // 80 bytes
#define ARR_BYTES (TM * ROWB)          // 10240 B per operand array
#define STAGE_BYTES (4 * ARR_BYTES)    // 40960 B per stage
#define NSTAGE 3
#define GEMM_SMEM (NSTAGE * STAGE_BYTES + (2 * TN + 2 * TM) * 4)   // 124928 B

__global__ void __launch_bounds__(256)
k_gemm(const float* __restrict__ Vv, float* __restrict__ score) {
    extern __shared__ __half smh[];
    float* sV   = (float*)((char*)smh + NSTAGE * STAGE_BYTES);   // [128]
    float* sW   = sV + TN;                                       // [128]
    float* sred = sW + TN;                                       // [128][2]

    const int tid = threadIdx.x;
    const int wid = tid >> 5;
    const int lane = tid & 31;
    const int tig = lane & 3;          // 0..3
    const int wm  = wid >> 1;          // 0..3  (m: 32 rows each)
    const int wn  = wid & 1;           // 0..1  (n: 64 cols each)

    const int s0 = blockIdx.x * TM;
    const int h0 = blockIdx.y * TN;
    const int b  = blockIdx.z;

    // Stage V and wq tiles
    if (tid < TN) {
        sV[tid] = Vv[h0 + tid];
        sW[tid] = g_wq[b * Hn + h0 + tid];
    }

    const uint32_t smb = smem_u32(smh);

    // --- cp.async task mapping: 4 tasks/thread/array, 8B each ---
    size_t aOff[4], bOff[4];
    uint32_t sOff[4];
    #pragma unroll
    for (int it = 0; it < 4; it++) {
        const int task = tid + 256 * it;
        const int trow = task >> 3;
        const int tseg = task & 7;
        aOff[it] = ((size_t)(b * Sn + s0 + trow)) * En + tseg * 4;  // halfs
        bOff[it] = ((size_t)(h0 + trow)) * En + tseg * 4;
        sOff[it] = trow * ROWB + tseg * 8;                          // bytes
    }

    // --- ldmatrix lane-address bases (stage 0, ks 0) ---
    // A (mt tile 16x16): lanes 0-7 rows mr+0..7 k+0 | 8-15 rows mr+8..15 k+0
    //                  | 16-23 rows mr+0..7 k+8 | 24-31 rows mr+8..15 k+8
    // -> regs {a0,a1,a2,a3} in mma order.
    uint32_t aBase[2][2], bBase[4][2];
    {
        const int rA = lane & 15;
        const uint32_t cA = (uint32_t)(lane >> 4) << 4;   // 0 or 16 bytes
        #pragma unroll
        for (int mt = 0; mt < 2; mt++) {
            const int row = wm * 32 + mt * 16 + rA;
            aBase[mt][0] = smb + 0 * ARR_BYTES + row * ROWB + cA;
            aBase[mt][1] = smb + 1 * ARR_BYTES + row * ROWB + cA;
        }
        // B (q covers nt=2q,2q+1): lanes 0-7 rows nb+0..7 k+0 | 8-15 same rows k+8
        //                        | 16-23 rows nb+8..15 k+0 | 24-31 same k+8
        // -> regs {b0(nt),b1(nt),b0(nt+1),b1(nt+1)}.
        const int rB = ((lane >> 4) << 3) + (lane & 7);
        const uint32_t cB = (uint32_t)(lane & 8) << 1;    // 0 or 16 bytes
        #pragma unroll
        for (int q = 0; q < 4; q++) {
            const int row = wn * 64 + q * 16 + rB;
            bBase[q][0] = smb + 2 * ARR_BYTES + row * ROWB + cB;
            bBase[q][1] = smb + 3 * ARR_BYTES + row * ROWB + cB;
        }
    }

    float acc[2][8][4];
    #pragma unroll
    for (int mt = 0; mt < 2; mt++)
        #pragma unroll
        for (int nt = 0; nt < 8; nt++)
            #pragma unroll
            for (int r = 0; r < 4; r++) acc[mt][nt][r] = 0.f;

    const int NCHUNK = En / TK;   // 32

    auto issue = [&](int c, int st) {
        const uint32_t base = smb + st * STAGE_BYTES;
        const size_t ck = (size_t)c * TK;   // halfs
        #pragma unroll
        for (int it = 0; it < 4; it++) {
            CP_ASYNC8(base + sOff[it],                 (const char*)&g_ench[aOff[it] + ck]);
            CP_ASYNC8(base + ARR_BYTES + sOff[it],     (const char*)&g_encl[aOff[it] + ck]);
            CP_ASYNC8(base + 2 * ARR_BYTES + sOff[it], (const char*)&g_wkh[bOff[it] + ck]);
            CP_ASYNC8(base + 3 * ARR_BYTES + sOff[it], (const char*)&g_wkl[bOff[it] + ck]);
        }
    };

    issue(0, 0); CP_COMMIT();
    issue(1, 1); CP_COMMIT();

    for (int c = 0; c < NCHUNK; c++) {
        const int st = c - (c / NSTAGE) * NSTAGE;     // c % 3
        if (c == NCHUNK - 1) { CP_WAIT0(); } else { CP_WAIT1(); }
        __syncthreads();      // stage st ready everywhere; stage (c+2)%3 free
        if (c + 2 < NCHUNK) {
            const int nx = c + 2;
            issue(nx, nx - (nx / NSTAGE) * NSTAGE);
            CP_COMMIT();
        }

        const uint32_t stOff = st * STAGE_BYTES;
        #pragma unroll
        for (int ks = 0; ks < 2; ks++) {
            const uint32_t off = stOff + ks * 32;     // 16 halfs
            uint32_t aH[2][4], aL[2][4], bH[4][4], bL[4][4];
            #pragma unroll
            for (int mt = 0; mt < 2; mt++) {
                LDSM_X4(aH[mt], aBase[mt][0] + off);
                LDSM_X4(aL[mt], aBase[mt][1] + off);
            }
            #pragma unroll
            for (int q = 0; q < 4; q++) {
                LDSM_X4(bH[q], bBase[q][0] + off);
                LDSM_X4(bL[q], bBase[q][1] + off);
            }
            #pragma unroll
            for (int mt = 0; mt < 2; mt++)
                #pragma unroll
                for (int q = 0; q < 4; q++) {
                    mma_f16(acc[mt][2 * q],     aH[mt], bH[q][0], bH[q][1]); // hh
                    mma_f16(acc[mt][2 * q + 1], aH[mt], bH[q][2], bH[q][3]);
                    mma_f16(acc[mt][2 * q],     aH[mt], bL[q][0], bL[q][1]); // hl
                    mma_f16(acc[mt][2 * q + 1], aH[mt], bL[q][2], bL[q][3]);
                    mma_f16(acc[mt][2 * q],     aL[mt], bH[q][0], bH[q][1]); // lh
                    mma_f16(acc[mt][2 * q + 1], aL[mt], bH[q][2], bH[q][3]);
                }
        }
    }

    // ---- Epilogue: score[b, s] += sum_h V[h]*tanh(ctx/1024 + wq[h]) ----
    const int g = lane >> 2;
    const float inv_sc = 1.0f / 1024.0f;
    float p[4] = {0.f, 0.f, 0.f, 0.f};
    #pragma unroll
    for (int mt = 0; mt < 2; mt++)
        #pragma unroll
        for (int nt = 0; nt < 8; nt++) {
            const int hl = wn * 64 + nt * 8 + 2 * tig;
            const float v0 = sV[hl], v1 = sV[hl + 1];
            const float w0 = sW[hl], w1 = sW[hl + 1];
            p[mt * 2 + 0] += v0 * tanh_fast(acc[mt][nt][0] * inv_sc + w0)
                           + v1 * tanh_fast(acc[mt][nt][1] * inv_sc + w1);
            p[mt * 2 + 1] += v0 * tanh_fast(acc[mt][nt][2] * inv_sc + w0)
                           + v1 * tanh_fast(acc[mt][nt][3] * inv_sc + w1);
        }
    #pragma unroll
    for (int o = 1; o < 4; o <<= 1) {
        #pragma unroll
        for (int i = 0; i < 4; i++)
            p[i] += __shfl_xor_sync(0xFFFFFFFFu, p[i], o);
    }
    if (tig == 0) {
        #pragma unroll
        for (int mt = 0; mt < 2; mt++)
            #pragma unroll
            for (int hf = 0; hf < 2; hf++) {
                const int r = wm * 32 + mt * 16 + hf * 8 + g;
                sred[r * 2 + wn] = p[mt * 2 + hf];
            }
    }
    __syncthreads();
    if (tid < TM)
        atomicAdd(&score[b * Sn + s0 + tid], sred[tid * 2] + sred[tid * 2 + 1]);
}

// ---------------------------------------------------------------------------
// Kernel 3: per-batch softmax over S -> g_alpha; also zero g_u.
// ---------------------------------------------------------------------------
__global__ void k_softmax(const float* __restrict__ score) {
    __shared__ float sh[256];
    const int b = blockIdx.x;
    const int tid = threadIdx.x;

    float vals[8];
    float lmax = -3.4e38f;
    #pragma unroll
    for (int i = 0; i < 8; i++) {
        vals[i] = score[b * Sn + tid + i * 256];
        lmax = fmaxf(lmax, vals[i]);
    }
    sh[tid] = lmax;
    __syncthreads();
    for (int off = 128; off > 0; off >>= 1) {
        if (tid < off) sh[tid] = fmaxf(sh[tid], sh[tid + off]);
        __syncthreads();
    }
    const float m = sh[0];
    __syncthreads();

    float lsum = 0.f;
    #pragma unroll
    for (int i = 0; i < 8; i++) {
        vals[i] = __expf(vals[i] - m);
        lsum += vals[i];
    }
    sh[tid] = lsum;
    __syncthreads();
    for (int off = 128; off > 0; off >>= 1) {
        if (tid < off) sh[tid] += sh[tid + off];
        __syncthreads();
    }
    const float inv = 1.0f / sh[0];
    #pragma unroll
    for (int i = 0; i < 8; i++)
        g_alpha[b * Sn + tid + i * 256] = vals[i] * inv;

    for (int e = tid; e < En; e += 256) g_u[b * En + e] = 0.f;
}

// ---------------------------------------------------------------------------
// Kernel 4: u[b,e] = sum_s alpha[b,s] * enc[b,s,e]
// ---------------------------------------------------------------------------
__global__ void k_wenc(const float* __restrict__ enc) {
    const int b  = blockIdx.z;
    const int sc = blockIdx.y * 64;
    const int e0 = blockIdx.x * 512 + threadIdx.x * 4;

    const float* ep = enc + ((size_t)b * Sn + sc) * En + e0;
    const float* ap = g_alpha + b * Sn + sc;

    float4 acc = make_float4(0.f, 0.f, 0.f, 0.f);
    #pragma unroll 4
    for (int s = 0; s < 64; s++) {
        float a = ap[s];
        float4 v = *(const float4*)(ep + (size_t)s * En);
        acc.x += a * v.x; acc.y += a * v.y;
        acc.z += a * v.z; acc.w += a * v.w;
    }
    atomicAdd(&g_u[b * En + e0 + 0], acc.x);
    atomicAdd(&g_u[b * En + e0 + 1], acc.y);
    atomicAdd(&g_u[b * En + e0 + 2], acc.z);
    atomicAdd(&g_u[b * En + e0 + 3], acc.w);
}

// ---------------------------------------------------------------------------
// Kernel 5: hidden[b,h] = W_k[h,:] . u[b,:]
// ---------------------------------------------------------------------------
__global__ void k_hidden(const float* __restrict__ Wk, float* __restrict__ hid) {
    __shared__ float us[En];
    const int b = blockIdx.y;
    const int h = blockIdx.x * 128 + threadIdx.x;

    #pragma unroll
    for (int e = threadIdx.x * 4; e < En; e += 512)
        *(float4*)&us[e] = *(const float4*)&g_u[b * En + e];
    __syncthreads();

    const float* w = Wk + (size_t)h * En;
    float acc = 0.f;
    #pragma unroll 4
    for (int e = 0; e < En; e += 4) {
        float4 w4 = *(const float4*)&w[e];
        acc += w4.x * us[e] + w4.y * us[e + 1] + w4.z * us[e + 2] + w4.w * us[e + 3];
    }
    hid[b * Hn + h] = acc;
}

// ---------------------------------------------------------------------------
// Launch. Graph-capturable, allocation-free.
// Output layout: [ hidden_state (B*H) | score (B*S) ]
// ---------------------------------------------------------------------------
extern "C" void kernel_launch(void* const* d_in, const int* in_sizes, int n_in,
                              void* d_out, int out_size) {
    const float* enc = (const float*)d_in[0];   // [B,S,E]
    const float* dec = (const float*)d_in[1];   // [B,E]
    const float* Wk  = (const float*)d_in[2];   // [H,E]
    const float* Wq  = (const float*)d_in[3];   // [H,E]
    const float* V   = (const float*)d_in[4];   // [H]

    float* out   = (float*)d_out;
    float* hid   = out;              // B*H
    float* score = out + Bn * Hn;    // B*S

    static bool attr_set = false;
    if (!attr_set) {
        cudaFuncSetAttribute(k_gemm, cudaFuncAttributeMaxDynamicSharedMemorySize,
                             GEMM_SMEM);
        attr_set = true;
    }

    void *ench, *encl, *wkh, *wkl;
    cudaGetSymbolAddress(&ench, g_ench);
    cudaGetSymbolAddress(&encl, g_encl);
    cudaGetSymbolAddress(&wkh,  g_wkh);
    cudaGetSymbolAddress(&wkl,  g_wkl);

    const int encGroups = Bn * Sn * En / 16;   // 4,194,304
    const int wkGroups  = Hn * En / 16;        // 65,536
    k_prep<<<encGroups / 256, 256>>>(enc, (__half*)ench, (__half*)encl, encGroups, 1.0f);
    k_prep<<<wkGroups / 256, 256>>>(Wk, (__half*)wkh, (__half*)wkl, wkGroups, 1024.0f);

    k_wq<<<dim3(Hn / 128, Bn), 128>>>(dec, Wq, score);
    k_gemm<<<dim3(Sn / TM, Hn / TN, Bn), 256, GEMM_SMEM>>>(V, score);
    k_softmax<<<Bn, 256>>>(score);
    k_wenc<<<dim3(En / 512, Sn / 64, Bn), 128>>>(enc);
    k_hidden<<<dim3(Hn / 128, Bn), 128>>>(Wk, hid);
}

// round 7
// speedup vs baseline: 3.9960x; 1.1563x over previous
#include <cuda_runtime.h>
#include <cuda_fp16.h>
#include <cstdint>

// Problem dims (fixed by the reference)
#define Bn 32
#define Sn 2048
#define En 1024
#define Hn 1024

// ---------------------------------------------------------------------------
// Scratch (allocation-free rule: __device__ globals)
// ---------------------------------------------------------------------------
__device__ float g_wq[Bn * Hn];      // W_q(dec_hidden)  [B,H]
__device__ float g_alpha[Bn * Sn];   // softmax(score)   [B,S]
__device__ float g_u[Bn * En];       // enc^T * alpha    [B,E]
// fp16 hi/lo splits, canonical layout (k contiguous per row)
__device__ __align__(16) __half g_ench[(size_t)Bn * Sn * En];
__device__ __align__(16) __half g_encl[(size_t)Bn * Sn * En];
__device__ __align__(16) __half g_wkh[Hn * En];   // W_k * 1024
__device__ __align__(16) __half g_wkl[Hn * En];

// ---------------------------------------------------------------------------
// Helpers
// ---------------------------------------------------------------------------
__device__ __forceinline__ uint32_t smem_u32(const void* p) {
    uint32_t a;
    asm("{ .reg .u64 t; cvta.to.shared.u64 t, %1; cvt.u32.u64 %0, t; }" : "=r"(a) : "l"(p));
    return a;
}

// m16n8k16 fp16 mma, D += A*B (row.col), fp32 accumulate. sm_80 baseline PTX.
__device__ __forceinline__ void mma_f16(float* d, const uint32_t* a,
                                        uint32_t b0, uint32_t b1) {
    asm volatile(
        "mma.sync.aligned.m16n8k16.row.col.f32.f16.f16.f32 "
        "{%0,%1,%2,%3}, {%4,%5,%6,%7}, {%8,%9}, {%0,%1,%2,%3};"
        : "+f"(d[0]), "+f"(d[1]), "+f"(d[2]), "+f"(d[3])
        : "r"(a[0]), "r"(a[1]), "r"(a[2]), "r"(a[3]), "r"(b0), "r"(b1));
}

#define LDSM_X4(r, addr)                                                        \
    asm volatile("ldmatrix.sync.aligned.m8n8.x4.shared.b16 {%0,%1,%2,%3}, [%4];" \
        : "=r"((r)[0]), "=r"((r)[1]), "=r"((r)[2]), "=r"((r)[3]) : "r"(addr))

#define CP_ASYNC8(dst, src) \
    asm volatile("cp.async.ca.shared.global [%0], [%1], 8;" \
        :: "r"(dst), "l"(src) : "memory")
#define CP_COMMIT() asm volatile("cp.async.commit_group;" ::: "memory")
#define CP_WAIT0()  asm volatile("cp.async.wait_group 0;" ::: "memory")

// Accurate fast tanh: 1 - 2/(exp(2x)+1). abs err ~2e-6, 2 MUFU.
__device__ __forceinline__ float tanh_fast(float x) {
    float e = __expf(2.0f * x);
    return 1.0f - __fdividef(2.0f, e + 1.0f);
}

// Split two floats into (hi, lo) fp16 pairs, packed as half2.
__device__ __forceinline__ void h2_split(float x, float y, uint32_t& h, uint32_t& l) {
    __half2 hh = __floats2half2_rn(x, y);
    float2 hf = __half22float2(hh);
    __half2 ll = __floats2half2_rn(x - hf.x, y - hf.y);
    h = *(uint32_t*)&hh;
    l = *(uint32_t*)&ll;
}

// ---------------------------------------------------------------------------
// Kernel 0: fp32 -> (hi, lo) fp16, canonical order, optional scale.
// ---------------------------------------------------------------------------
__global__ void k_prep(const float* __restrict__ src, __half* __restrict__ dh,
                       __half* __restrict__ dl, int ngroups, float scale) {
    int gid = blockIdx.x * blockDim.x + threadIdx.x;
    if (gid >= ngroups) return;
    float f[16];
    const float4* s = (const float4*)(src + (size_t)gid * 16);
    *(float4*)&f[0]  = s[0];
    *(float4*)&f[4]  = s[1];
    *(float4*)&f[8]  = s[2];
    *(float4*)&f[12] = s[3];
    uint32_t oh[8], ol[8];
    #pragma unroll
    for (int t = 0; t < 8; t++)
        h2_split(f[2 * t] * scale, f[2 * t + 1] * scale, oh[t], ol[t]);
    uint4* ph = (uint4*)(dh + (size_t)gid * 16);
    uint4* pl = (uint4*)(dl + (size_t)gid * 16);
    ph[0] = make_uint4(oh[0], oh[1], oh[2], oh[3]);
    ph[1] = make_uint4(oh[4], oh[5], oh[6], oh[7]);
    pl[0] = make_uint4(ol[0], ol[1], ol[2], ol[3]);
    pl[1] = make_uint4(ol[4], ol[5], ol[6], ol[7]);
}

// ---------------------------------------------------------------------------
// Kernel 1: wq[b,h] = dec[b,:] . W_q[h,:]   + zero the score output region
// ---------------------------------------------------------------------------
__global__ void k_wq(const float* __restrict__ dec,
                     const float* __restrict__ Wq,
                     float* __restrict__ score_out) {
    __shared__ float ds[En];
    const int b  = blockIdx.y;
    const int h0 = blockIdx.x * 128;
    const int tid = threadIdx.x;

    #pragma unroll
    for (int e = tid * 4; e < En; e += 512)
        *(float4*)&ds[e] = *(const float4*)&dec[b * En + e];

    float2 z = make_float2(0.f, 0.f);
    *(float2*)&score_out[b * Sn + blockIdx.x * 256 + tid * 2] = z;

    __syncthreads();

    const int h = h0 + tid;
    const float* w = Wq + (size_t)h * En;
    float acc = 0.f;
    #pragma unroll 4
    for (int e = 0; e < En; e += 4) {
        float4 w4 = *(const float4*)&w[e];
        acc += w4.x * ds[e] + w4.y * ds[e + 1] + w4.z * ds[e + 2] + w4.w * ds[e + 3];
    }
    g_wq[b * Hn + h] = acc;
}

// ---------------------------------------------------------------------------
// Kernel 2: fp16x3 GEMM + fused tanh/V epilogue.
// ldmatrix.x4, cp.async 2-stage, 2 CTAs/SM (smem 83456 B, <=128 regs).
// Tile 128(s) x 128(h) x 32(k). 256 threads = 8 warps (4m x 2n), warp 32x64.
// grid (Sn/128=16, Hn/128=8, Bn=32)
// ---------------------------------------------------------------------------
#define TM 128
#define TN 128
#define TK 32
#define ROWH 40                        // halfs per smem row (32 data + 8 pad, 80B)
#define ROWB (ROWH * 2)                // 80 bytes
#define ARR_BYTES (TM * ROWB)          // 10240 B per operand array
#define STAGE_BYTES (4 * ARR_BYTES)    // 40960 B per stage
#define NSTAGE 2
#define GEMM_SMEM (NSTAGE * STAGE_BYTES + (2 * TN + 2 * TM) * 4)   // 83456 B

__global__ void __launch_bounds__(256, 2)
k_gemm(const float* __restrict__ Vv, float* __restrict__ score) {
    extern __shared__ __half smh[];
    float* sV   = (float*)((char*)smh + NSTAGE * STAGE_BYTES);   // [128]
    float* sW   = sV + TN;                                       // [128]
    float* sred = sW + TN;                                       // [128][2]

    const int tid = threadIdx.x;
    const int wid = tid >> 5;
    const int lane = tid & 31;
    const int tig = lane & 3;          // 0..3
    const int wm  = wid >> 1;          // 0..3  (m: 32 rows each)
    const int wn  = wid & 1;           // 0..1  (n: 64 cols each)

    const int s0 = blockIdx.x * TM;
    const int h0 = blockIdx.y * TN;
    const int b  = blockIdx.z;

    // Stage V and wq tiles
    if (tid < TN) {
        sV[tid] = Vv[h0 + tid];
        sW[tid] = g_wq[b * Hn + h0 + tid];
    }

    const uint32_t smb = smem_u32(smh);

    // --- cp.async task mapping: 4 tasks/thread/array, 8B each ---
    size_t aOff[4], bOff[4];
    uint32_t sOff[4];
    #pragma unroll
    for (int it = 0; it < 4; it++) {
        const int task = tid + 256 * it;
        const int trow = task >> 3;
        const int tseg = task & 7;
        aOff[it] = ((size_t)(b * Sn + s0 + trow)) * En + tseg * 4;  // halfs
        bOff[it] = ((size_t)(h0 + trow)) * En + tseg * 4;
        sOff[it] = trow * ROWB + tseg * 8;                          // bytes
    }

    // --- ldmatrix lane-address bases (stage 0, ks 0) ---
    uint32_t aBase[2][2], bBase[4][2];
    {
        const int rA = lane & 15;
        const uint32_t cA = (uint32_t)(lane >> 4) << 4;   // 0 or 16 bytes
        #pragma unroll
        for (int mt = 0; mt < 2; mt++) {
            const int row = wm * 32 + mt * 16 + rA;
            aBase[mt][0] = smb + 0 * ARR_BYTES + row * ROWB + cA;
            aBase[mt][1] = smb + 1 * ARR_BYTES + row * ROWB + cA;
        }
        const int rB = ((lane >> 4) << 3) + (lane & 7);
        const uint32_t cB = (uint32_t)(lane & 8) << 1;    // 0 or 16 bytes
        #pragma unroll
        for (int q = 0; q < 4; q++) {
            const int row = wn * 64 + q * 16 + rB;
            bBase[q][0] = smb + 2 * ARR_BYTES + row * ROWB + cB;
            bBase[q][1] = smb + 3 * ARR_BYTES + row * ROWB + cB;
        }
    }

    float acc[2][8][4];
    #pragma unroll
    for (int mt = 0; mt < 2; mt++)
        #pragma unroll
        for (int nt = 0; nt < 8; nt++)
            #pragma unroll
            for (int r = 0; r < 4; r++) acc[mt][nt][r] = 0.f;

    const int NCHUNK = En / TK;   // 32

    auto issue = [&](int c, int st) {
        const uint32_t base = smb + st * STAGE_BYTES;
        const size_t ck = (size_t)c * TK;   // halfs
        #pragma unroll
        for (int it = 0; it < 4; it++) {
            CP_ASYNC8(base + sOff[it],                 (const char*)&g_ench[aOff[it] + ck]);
            CP_ASYNC8(base + ARR_BYTES + sOff[it],     (const char*)&g_encl[aOff[it] + ck]);
            CP_ASYNC8(base + 2 * ARR_BYTES + sOff[it], (const char*)&g_wkh[bOff[it] + ck]);
            CP_ASYNC8(base + 3 * ARR_BYTES + sOff[it], (const char*)&g_wkl[bOff[it] + ck]);
        }
    };

    issue(0, 0); CP_COMMIT();

    for (int c = 0; c < NCHUNK; c++) {
        const int st = c & 1;
        CP_WAIT0();
        __syncthreads();      // stage st ready everywhere; all warps past chunk c-1
        if (c + 1 < NCHUNK) {
            issue(c + 1, st ^ 1);
            CP_COMMIT();
        }

        const uint32_t stOff = st * STAGE_BYTES;
        #pragma unroll
        for (int ks = 0; ks < 2; ks++) {
            const uint32_t off = stOff + ks * 32;     // 16 halfs
            uint32_t aH[2][4], aL[2][4];
            #pragma unroll
            for (int mt = 0; mt < 2; mt++) {
                LDSM_X4(aH[mt], aBase[mt][0] + off);
                LDSM_X4(aL[mt], aBase[mt][1] + off);
            }
            #pragma unroll
            for (int q = 0; q < 4; q++) {
                uint32_t bH[4], bL[4];
                LDSM_X4(bH, bBase[q][0] + off);
                LDSM_X4(bL, bBase[q][1] + off);
                #pragma unroll
                for (int mt = 0; mt < 2; mt++) {
                    mma_f16(acc[mt][2 * q],     aH[mt], bH[0], bH[1]);   // hh
                    mma_f16(acc[mt][2 * q + 1], aH[mt], bH[2], bH[3]);
                    mma_f16(acc[mt][2 * q],     aH[mt], bL[0], bL[1]);   // hl
                    mma_f16(acc[mt][2 * q + 1], aH[mt], bL[2], bL[3]);
                    mma_f16(acc[mt][2 * q],     aL[mt], bH[0], bH[1]);   // lh
                    mma_f16(acc[mt][2 * q + 1], aL[mt], bH[2], bH[3]);
                }
            }
        }
        __syncthreads();      // all warps done with stage st before refill
    }

    // ---- Epilogue: score[b, s] += sum_h V[h]*tanh(ctx/1024 + wq[h]) ----
    const int g = lane >> 2;
    const float inv_sc = 1.0f / 1024.0f;
    float p[4] = {0.f, 0.f, 0.f, 0.f};
    #pragma unroll
    for (int mt = 0; mt < 2; mt++)
        #pragma unroll
        for (int nt = 0; nt < 8; nt++) {
            const int hl = wn * 64 + nt * 8 + 2 * tig;
            const float v0 = sV[hl], v1 = sV[hl + 1];
            const float w0 = sW[hl], w1 = sW[hl + 1];
            p[mt * 2 + 0] += v0 * tanh_fast(acc[mt][nt][0] * inv_sc + w0)
                           + v1 * tanh_fast(acc[mt][nt][1] * inv_sc + w1);
            p[mt * 2 + 1] += v0 * tanh_fast(acc[mt][nt][2] * inv_sc + w0)
                           + v1 * tanh_fast(acc[mt][nt][3] * inv_sc + w1);
        }
    #pragma unroll
    for (int o = 1; o < 4; o <<= 1) {
        #pragma unroll
        for (int i = 0; i < 4; i++)
            p[i] += __shfl_xor_sync(0xFFFFFFFFu, p[i], o);
    }
    if (tig == 0) {
        #pragma unroll
        for (int mt = 0; mt < 2; mt++)
            #pragma unroll
            for (int hf = 0; hf < 2; hf++) {
                const int r = wm * 32 + mt * 16 + hf * 8 + g;
                sred[r * 2 + wn] = p[mt * 2 + hf];
            }
    }
    __syncthreads();
    if (tid < TM)
        atomicAdd(&score[b * Sn + s0 + tid], sred[tid * 2] + sred[tid * 2 + 1]);
}

// ---------------------------------------------------------------------------
// Kernel 3: per-batch softmax over S -> g_alpha; also zero g_u.
// ---------------------------------------------------------------------------
__global__ void k_softmax(const float* __restrict__ score) {
    __shared__ float sh[256];
    const int b = blockIdx.x;
    const int tid = threadIdx.x;

    float vals[8];
    float lmax = -3.4e38f;
    #pragma unroll
    for (int i = 0; i < 8; i++) {
        vals[i] = score[b * Sn + tid + i * 256];
        lmax = fmaxf(lmax, vals[i]);
    }
    sh[tid] = lmax;
    __syncthreads();
    for (int off = 128; off > 0; off >>= 1) {
        if (tid < off) sh[tid] = fmaxf(sh[tid], sh[tid + off]);
        __syncthreads();
    }
    const float m = sh[0];
    __syncthreads();

    float lsum = 0.f;
    #pragma unroll
    for (int i = 0; i < 8; i++) {
        vals[i] = __expf(vals[i] - m);
        lsum += vals[i];
    }
    sh[tid] = lsum;
    __syncthreads();
    for (int off = 128; off > 0; off >>= 1) {
        if (tid < off) sh[tid] += sh[tid + off];
        __syncthreads();
    }
    const float inv = 1.0f / sh[0];
    #pragma unroll
    for (int i = 0; i < 8; i++)
        g_alpha[b * Sn + tid + i * 256] = vals[i] * inv;

    for (int e = tid; e < En; e += 256) g_u[b * En + e] = 0.f;
}

// ---------------------------------------------------------------------------
// Kernel 4: u[b,e] = sum_s alpha[b,s] * enc[b,s,e]
// ---------------------------------------------------------------------------
__global__ void k_wenc(const float* __restrict__ enc) {
    const int b  = blockIdx.z;
    const int sc = blockIdx.y * 64;
    const int e0 = blockIdx.x * 512 + threadIdx.x * 4;

    const float* ep = enc + ((size_t)b * Sn + sc) * En + e0;
    const float* ap = g_alpha + b * Sn + sc;

    float4 acc = make_float4(0.f, 0.f, 0.f, 0.f);
    #pragma unroll 4
    for (int s = 0; s < 64; s++) {
        float a = ap[s];
        float4 v = *(const float4*)(ep + (size_t)s * En);
        acc.x += a * v.x; acc.y += a * v.y;
        acc.z += a * v.z; acc.w += a * v.w;
    }
    atomicAdd(&g_u[b * En + e0 + 0], acc.x);
    atomicAdd(&g_u[b * En + e0 + 1], acc.y);
    atomicAdd(&g_u[b * En + e0 + 2], acc.z);
    atomicAdd(&g_u[b * En + e0 + 3], acc.w);
}

// ---------------------------------------------------------------------------
// Kernel 5: hidden[b,h] = W_k[h,:] . u[b,:]
// ---------------------------------------------------------------------------
__global__ void k_hidden(const float* __restrict__ Wk, float* __restrict__ hid) {
    __shared__ float us[En];
    const int b = blockIdx.y;
    const int h = blockIdx.x * 128 + threadIdx.x;

    #pragma unroll
    for (int e = threadIdx.x * 4; e < En; e += 512)
        *(float4*)&us[e] = *(const float4*)&g_u[b * En + e];
    __syncthreads();

    const float* w = Wk + (size_t)h * En;
    float acc = 0.f;
    #pragma unroll 4
    for (int e = 0; e < En; e += 4) {
        float4 w4 = *(const float4*)&w[e];
        acc += w4.x * us[e] + w4.y * us[e + 1] + w4.z * us[e + 2] + w4.w * us[e + 3];
    }
    hid[b * Hn + h] = acc;
}

// ---------------------------------------------------------------------------
// Launch. Graph-capturable, allocation-free.
// Output layout: [ hidden_state (B*H) | score (B*S) ]
// ---------------------------------------------------------------------------
extern "C" void kernel_launch(void* const* d_in, const int* in_sizes, int n_in,
                              void* d_out, int out_size) {
    const float* enc = (const float*)d_in[0];   // [B,S,E]
    const float* dec = (const float*)d_in[1];   // [B,E]
    const float* Wk  = (const float*)d_in[2];   // [H,E]
    const float* Wq  = (const float*)d_in[3];   // [H,E]
    const float* V   = (const float*)d_in[4];   // [H]

    float* out   = (float*)d_out;
    float* hid   = out;              // B*H
    float* score = out + Bn * Hn;    // B*S

    static bool attr_set = false;
    if (!attr_set) {
        cudaFuncSetAttribute(k_gemm, cudaFuncAttributeMaxDynamicSharedMemorySize,
                             GEMM_SMEM);
        attr_set = true;
    }

    void *ench, *encl, *wkh, *wkl;
    cudaGetSymbolAddress(&ench, g_ench);
    cudaGetSymbolAddress(&encl, g_encl);
    cudaGetSymbolAddress(&wkh,  g_wkh);
    cudaGetSymbolAddress(&wkl,  g_wkl);

    const int encGroups = Bn * Sn * En / 16;   // 4,194,304
    const int wkGroups  = Hn * En / 16;        // 65,536
    k_prep<<<encGroups / 256, 256>>>(enc, (__half*)ench, (__half*)encl, encGroups, 1.0f);
    k_prep<<<wkGroups / 256, 256>>>(Wk, (__half*)wkh, (__half*)wkl, wkGroups, 1024.0f);

    k_wq<<<dim3(Hn / 128, Bn), 128>>>(dec, Wq, score);
    k_gemm<<<dim3(Sn / TM, Hn / TN, Bn), 256, GEMM_SMEM>>>(V, score);
    k_softmax<<<Bn, 256>>>(score);
    k_wenc<<<dim3(En / 512, Sn / 64, Bn), 128>>>(enc);
    k_hidden<<<dim3(Hn / 128, Bn), 128>>>(Wk, hid);
}